// round 10
// baseline (speedup 1.0000x reference)
#include <cuda_runtime.h>
#include <cuda_fp16.h>
#include <math.h>
#include <stdint.h>

// ---------------------------------------------------------------------------
// TextGRUClassifier: 2-layer bidir GRU (B=256,T=512,E=128,H=160) + FC head
// R10 = R7 sequential skeleton (no cross-kernel overlap — R8/R9 showed spin
// overlap is stale-read-prone and hangs serialized profiling) plus:
//   - gi0/gi1/y0 stored in fp16 (compute stays tf32 mma + fp32 accum)
//   - k-permuted float2 fragment loads in the GEMMs
//   - scan gi staging via 16B row-wise cp.async (fp16)
// ---------------------------------------------------------------------------

#define Tt 512
#define Bb 256
#define Hh 160
#define G3 480
#define Mrows (Tt*Bb)     // 131072

// ---- scratch ----
static __device__ __half g_gi0[(size_t)2 * Mrows * G3];  // [dir][t][n=480][b=256]
static __device__ __half g_gi1[(size_t)2 * Mrows * G3];
static __device__ __half g_y0[(size_t)Mrows * 320];      // [t][n=320][b=256]
static __device__ float  g_hfin[2 * Bb * Hh];            // [dir][b][g]

// ---- helpers ----
__device__ __forceinline__ float tanh_ap(float x) {
    float r;
    asm("tanh.approx.f32 %0, %1;" : "=f"(r) : "f"(x));
    return r;
}
__device__ __forceinline__ uint32_t f2tf32(float x) {
    uint32_t r;
    asm("cvt.rna.tf32.f32 %0, %1;" : "=r"(r) : "f"(x));
    return r;
}
__device__ __forceinline__ float tf32f(float x) { return __uint_as_float(f2tf32(x)); }
__device__ __forceinline__ void mma_tf32(float* d, const uint32_t* a, const uint32_t* b) {
    asm volatile(
        "mma.sync.aligned.m16n8k8.row.col.f32.tf32.tf32.f32 "
        "{%0,%1,%2,%3}, {%4,%5,%6,%7}, {%8,%9}, {%0,%1,%2,%3};"
        : "+f"(d[0]), "+f"(d[1]), "+f"(d[2]), "+f"(d[3])
        : "r"(a[0]), "r"(a[1]), "r"(a[2]), "r"(a[3]), "r"(b[0]), "r"(b[1]));
}
__device__ __forceinline__ uint32_t smem_u32(const void* p) {
    uint32_t a;
    asm("{ .reg .u64 t; cvta.to.shared.u64 t, %1; cvt.u32.u64 %0, t; }" : "=r"(a) : "l"(p));
    return a;
}
__device__ __forceinline__ uint32_t mapa_peer(uint32_t addr, uint32_t rank) {
    uint32_t r;
    asm("mapa.shared::cluster.u32 %0, %1, %2;" : "=r"(r) : "r"(addr), "r"(rank));
    return r;
}
__device__ __forceinline__ void st_cluster_u32(uint32_t addr, uint32_t v) {
    asm volatile("st.shared::cluster.u32 [%0], %1;" :: "r"(addr), "r"(v) : "memory");
}
__device__ __forceinline__ void cp_async16(uint32_t dst, const void* src) {
    asm volatile("cp.async.ca.shared.global [%0], [%1], 16;" :: "r"(dst), "l"(src) : "memory");
}
__device__ __forceinline__ void cp_commit() {
    asm volatile("cp.async.commit_group;" ::: "memory");
}
__device__ __forceinline__ void cp_wait1() {
    asm volatile("cp.async.wait_group 1;" ::: "memory");
}
__device__ __forceinline__ void mbar_init(uint32_t addr, uint32_t count) {
    asm volatile("mbarrier.init.shared.b64 [%0], %1;" :: "r"(addr), "r"(count) : "memory");
}
__device__ __forceinline__ void mbar_arrive_peer(uint32_t remote_addr) {
    asm volatile("mbarrier.arrive.release.cluster.shared::cluster.b64 _, [%0];"
                 :: "r"(remote_addr) : "memory");
}
__device__ __forceinline__ void mbar_wait_parity(uint32_t addr, uint32_t parity) {
    uint32_t done;
    asm volatile(
        "{\n\t.reg .pred p;\n\t"
        "mbarrier.try_wait.parity.acquire.cluster.shared::cta.b64 p, [%1], %2;\n\t"
        "selp.b32 %0, 1, 0, p;\n\t}"
        : "=r"(done) : "r"(addr), "r"(parity) : "memory");
    if (!done) {
        asm volatile(
            "{\n\t.reg .pred P1;\n\t"
            "WAIT_LOOP_%=:\n\t"
            "mbarrier.try_wait.parity.acquire.cluster.shared::cta.b64 P1, [%0], %1, 0x989680;\n\t"
            "@P1 bra.uni WAIT_DONE_%=;\n\t"
            "bra.uni WAIT_LOOP_%=;\n\t"
            "WAIT_DONE_%=:\n\t}"
            :: "r"(addr), "r"(parity) : "memory");
    }
}
#define CLUSTER_SYNC() do { \
    asm volatile("barrier.cluster.arrive.aligned;" ::: "memory"); \
    asm volatile("barrier.cluster.wait.aligned;" ::: "memory"); \
} while (0)

// ---------------------------------------------------------------------------
// K1/K3: gates GEMM on tf32 tensor cores.
//   out (half): [dir][t][n=480][b=256].
//   GATHER (layer0): A = emb rows (fp32) via x; As [m][ALD] with permuted k.
//   layer1: A = y0 (half) [t][k=320][256]; As [k][MLD] floats.
//   Bs always [n][ALD] with permuted k slots [k0 k4 k1 k5 k2 k6 k3 k7] so a
//   fragment k-pair (tq, tq+4) loads as one float2.
// ---------------------------------------------------------------------------
#define ALD 36
#define MLD 136

template <int KDIM, bool GATHER>
__global__ __launch_bounds__(256, 2)
void gates_mma_kernel(const void* __restrict__ Avoid, const int* __restrict__ xids,
                      const float* __restrict__ Wf, const float* __restrict__ Wb,
                      const float* __restrict__ bf, const float* __restrict__ bb,
                      __half* __restrict__ out) {
    const int m0 = blockIdx.x * 128;
    const int n0 = blockIdx.y * 96;
    const int dir = blockIdx.z;
    const float* W = dir ? Wb : Wf;
    const float* bias = dir ? bb : bf;
    __half* outp = out + (size_t)dir * Mrows * G3;

    __shared__ __align__(16) float As[128 * ALD];   // GATHER path uses 128*36=4608; layer1 uses 32*136=4352
    __shared__ __align__(16) float Bs[96 * ALD];
    __shared__ int rid[128];

    const int tid = threadIdx.x;
    if (GATHER) {
        if (tid < 128) {
            int m = m0 + tid;
            rid[tid] = xids[(m & 255) * Tt + (m >> 8)];
        }
        __syncthreads();
    }

    const int lane = tid & 31, wid = tid >> 5;
    const int grp = lane >> 2, tq = lane & 3;
    const int m_off = (wid >> 1) * 32;
    const int n_off = (wid & 1) * 48;

    float acc[2][6][4];
#pragma unroll
    for (int i = 0; i < 2; i++)
#pragma unroll
        for (int j = 0; j < 6; j++)
#pragma unroll
            for (int c = 0; c < 4; c++) acc[i][j][c] = 0.f;

    const int rA = tid >> 3;       // 0..31
    const int cA = tid & 7;        // 0..7
    const int pslot = (cA >> 1) * 8 + (cA & 1);   // permuted base slot

    // ---- A sources ----
    const float* arow[4];
    if (GATHER) {
        const float* Af = (const float*)Avoid;
#pragma unroll
        for (int u = 0; u < 4; u++) arow[u] = Af + (size_t)rid[rA + u * 32] * KDIM;
    }
    const __half* AbaseH = GATHER ? nullptr
        : (const __half*)Avoid + ((size_t)(m0 >> 8) * KDIM) * 256 + (m0 & 255);

    const float* brow[3];
#pragma unroll
    for (int u = 0; u < 3; u++) brow[u] = W + (size_t)(n0 + rA + u * 32) * KDIM;

    const int KT = KDIM / 32;
    float4 aR[4], bR[3];
    uint4 aRh[2];
    // layer1 staging coords: idx = u*256 + tid (u<2): k = idx>>4, m8 = (idx&15)*8
    const int kH0 = tid >> 4;            // u=0 k
    const int kH1 = (256 + tid) >> 4;    // u=1 k
    const int mH = (tid & 15) * 8;

    // prologue: load tile 0
    if (GATHER) {
#pragma unroll
        for (int u = 0; u < 4; u++) aR[u] = *(const float4*)(arow[u] + cA * 4);
    } else {
        aRh[0] = *(const uint4*)(AbaseH + (size_t)kH0 * 256 + mH);
        aRh[1] = *(const uint4*)(AbaseH + (size_t)kH1 * 256 + mH);
    }
#pragma unroll
    for (int u = 0; u < 3; u++) bR[u] = *(const float4*)(brow[u] + cA * 4);

    for (int kt = 0; kt < KT; kt++) {
        __syncthreads();
        if (GATHER) {
#pragma unroll
            for (int u = 0; u < 4; u++) {
                float4 v = aR[u];
                float* ap = &As[(rA + u * 32) * ALD + pslot];
                ap[0] = tf32f(v.x);
                ap[2] = tf32f(v.y);
                ap[4] = tf32f(v.z);
                ap[6] = tf32f(v.w);
            }
        } else {
#pragma unroll
            for (int u = 0; u < 2; u++) {
                int k = u ? kH1 : kH0;
                const __half2* hp = (const __half2*)&aRh[u];
                float f[8];
#pragma unroll
                for (int q = 0; q < 4; q++) {
                    float2 fv = __half22float2(hp[q]);
                    f[2 * q]     = tf32f(fv.x);
                    f[2 * q + 1] = tf32f(fv.y);
                }
                *(float4*)&As[k * MLD + mH]     = make_float4(f[0], f[1], f[2], f[3]);
                *(float4*)&As[k * MLD + mH + 4] = make_float4(f[4], f[5], f[6], f[7]);
            }
        }
#pragma unroll
        for (int u = 0; u < 3; u++) {
            float4 v = bR[u];
            float* bp = &Bs[(rA + u * 32) * ALD + pslot];
            bp[0] = tf32f(v.x);
            bp[2] = tf32f(v.y);
            bp[4] = tf32f(v.z);
            bp[6] = tf32f(v.w);
        }
        __syncthreads();

        if (kt + 1 < KT) {
            int ko = (kt + 1) * 32;
            if (GATHER) {
#pragma unroll
                for (int u = 0; u < 4; u++) aR[u] = *(const float4*)(arow[u] + ko + cA * 4);
            } else {
                aRh[0] = *(const uint4*)(AbaseH + (size_t)(ko + kH0) * 256 + mH);
                aRh[1] = *(const uint4*)(AbaseH + (size_t)(ko + kH1) * 256 + mH);
            }
#pragma unroll
            for (int u = 0; u < 3; u++) bR[u] = *(const float4*)(brow[u] + ko + cA * 4);
        }

#pragma unroll
        for (int kc = 0; kc < 4; kc++) {
            uint32_t af[2][4];
            if (GATHER) {
#pragma unroll
                for (int i = 0; i < 2; i++) {
                    int rm = m_off + i * 16;
                    float2 p0 = *(const float2*)&As[(rm + grp) * ALD + kc * 8 + tq * 2];
                    float2 p1 = *(const float2*)&As[(rm + 8 + grp) * ALD + kc * 8 + tq * 2];
                    af[i][0] = __float_as_uint(p0.x);
                    af[i][1] = __float_as_uint(p1.x);
                    af[i][2] = __float_as_uint(p0.y);
                    af[i][3] = __float_as_uint(p1.y);
                }
            } else {
                const int kk0 = kc * 8;
#pragma unroll
                for (int i = 0; i < 2; i++) {
                    int rm = m_off + i * 16;
                    af[i][0] = __float_as_uint(As[(kk0 + tq) * MLD + rm + grp]);
                    af[i][1] = __float_as_uint(As[(kk0 + tq) * MLD + rm + 8 + grp]);
                    af[i][2] = __float_as_uint(As[(kk0 + tq + 4) * MLD + rm + grp]);
                    af[i][3] = __float_as_uint(As[(kk0 + tq + 4) * MLD + rm + 8 + grp]);
                }
            }
            uint32_t bfr[6][2];
#pragma unroll
            for (int j = 0; j < 6; j++) {
                int nb = n_off + j * 8;
                float2 pb = *(const float2*)&Bs[(nb + grp) * ALD + kc * 8 + tq * 2];
                bfr[j][0] = __float_as_uint(pb.x);
                bfr[j][1] = __float_as_uint(pb.y);
            }
#pragma unroll
            for (int i = 0; i < 2; i++)
#pragma unroll
                for (int j = 0; j < 6; j++) mma_tf32(acc[i][j], af[i], bfr[j]);
        }
    }

    // epilogue -> half out[t][n][256]
    {
        const int t_t = m0 >> 8;
        const int bb = m0 & 255;
        __half* ob = outp + (size_t)t_t * G3 * 256 + bb;
#pragma unroll
        for (int j = 0; j < 6; j++) {
            int col = n0 + n_off + j * 8 + 2 * tq;
            float b0v = bias[col], b1v = bias[col + 1];
#pragma unroll
            for (int i = 0; i < 2; i++) {
                int ml = m_off + i * 16 + grp;
                ob[(size_t)col * 256 + ml]           = __float2half(acc[i][j][0] + b0v);
                ob[(size_t)(col + 1) * 256 + ml]     = __float2half(acc[i][j][1] + b1v);
                ob[(size_t)col * 256 + ml + 8]       = __float2half(acc[i][j][2] + b0v);
                ob[(size_t)(col + 1) * 256 + ml + 8] = __float2half(acc[i][j][3] + b1v);
            }
        }
    }
}

// ---------------------------------------------------------------------------
// K2/K4: GRU scan on tensor cores, 2-CTA cluster (R7 structure):
//   k-split mma around the peer mbar wait; tanh.approx gates; gi (half)
//   staged one step ahead via 240 row-wise 16B cp.asyncs.
// ---------------------------------------------------------------------------
#define HST 168                  // h row stride (floats); 168 % 32 == 8
#define HBUFN (8 * HST)
#define GROWS 240                // gi rows staged per step (3 gates x 80 units)

__global__ __launch_bounds__(512) __cluster_dims__(2, 1, 1)
void scan_mma_kernel(const __half* __restrict__ gi,
                     const float* __restrict__ whhF, const float* __restrict__ whhB,
                     const float* __restrict__ bhf, const float* __restrict__ bhb,
                     void* __restrict__ yout, int layer) {
    __shared__ __align__(16) float hbuf[2][HBUFN];   // [buf][b][perm(k)] (tf32 bits)
    __shared__ float gh[240 * 8];                    // [lr][b]
    __shared__ __align__(16) __half gis[2][GROWS * 8];
    __shared__ __align__(8) unsigned long long mbar[2];

    const int dir = blockIdx.y;
    const int rank = blockIdx.x & 1;
    const int b0 = (blockIdx.x >> 1) * 8;
    const int tid = threadIdx.x;
    const int wid = tid >> 5, lane = tid & 31;
    const int grp = lane >> 2, tq = lane & 3;

    const uint32_t mbar0 = smem_u32(&mbar[0]);
    const uint32_t mbar1 = smem_u32(&mbar[1]);
    const uint32_t pbar0 = mapa_peer(mbar0, rank ^ 1);
    const uint32_t pbar1 = mapa_peer(mbar1, rank ^ 1);
    if (tid == 0) {
        mbar_init(mbar0, 1);
        mbar_init(mbar1, 1);
    }

    // ---- preload Whh A-fragments: [0..39] own-rank k half, [40..79] peer half ----
    uint32_t wreg[80];
    const bool is_mma = (wid < 15);
    const int ktL = rank * 10;
    const int ktR = (rank ^ 1) * 10;
    if (is_mma) {
        const int gate = wid / 5, mseg = wid % 5;
        const int gr0 = gate * Hh + rank * 80 + mseg * 16 + grp;
        const float* W = dir ? whhB : whhF;
#pragma unroll
        for (int j = 0; j < 10; j++) {
            int kt = ktL + j;
            wreg[j * 4 + 0] = f2tf32(W[(size_t)gr0 * Hh + kt * 8 + tq]);
            wreg[j * 4 + 1] = f2tf32(W[(size_t)(gr0 + 8) * Hh + kt * 8 + tq]);
            wreg[j * 4 + 2] = f2tf32(W[(size_t)gr0 * Hh + kt * 8 + tq + 4]);
            wreg[j * 4 + 3] = f2tf32(W[(size_t)(gr0 + 8) * Hh + kt * 8 + tq + 4]);
        }
#pragma unroll
        for (int j = 0; j < 10; j++) {
            int kt = ktR + j;
            wreg[40 + j * 4 + 0] = f2tf32(W[(size_t)gr0 * Hh + kt * 8 + tq]);
            wreg[40 + j * 4 + 1] = f2tf32(W[(size_t)(gr0 + 8) * Hh + kt * 8 + tq]);
            wreg[40 + j * 4 + 2] = f2tf32(W[(size_t)gr0 * Hh + kt * 8 + tq + 4]);
            wreg[40 + j * 4 + 3] = f2tf32(W[(size_t)(gr0 + 8) * Hh + kt * 8 + tq + 4]);
        }
    }

    // ---- combine-item setup ----
    const int uA = tid >> 3, bA = tid & 7;      // uA in 0..63 = unit-local
    const int gA = rank * 80 + uA;
    const int pgA = (gA & ~7) | (((gA & 3) << 1) | ((gA >> 2) & 1));
    const float* bh = dir ? bhb : bhf;
    const float bhrA = bh[gA], bhzA = bh[Hh + gA], bhnA = bh[2 * Hh + gA];
    uint32_t prA[2];
    prA[0] = mapa_peer(smem_u32(&hbuf[0][bA * HST + pgA]), rank ^ 1);
    prA[1] = mapa_peer(smem_u32(&hbuf[1][bA * HST + pgA]), rank ^ 1);

    const bool hasB = (tid < 128);
    const int uB = 64 + (tid >> 3), gB = rank * 80 + uB;
    const int pgB = (gB & ~7) | (((gB & 3) << 1) | ((gB >> 2) & 1));
    float bhrB = 0.f, bhzB = 0.f, bhnB = 0.f;
    uint32_t prB[2] = {0u, 0u};
    if (hasB) {
        bhrB = bh[gB]; bhzB = bh[Hh + gB]; bhnB = bh[2 * Hh + gB];
        prB[0] = mapa_peer(smem_u32(&hbuf[0][bA * HST + pgB]), rank ^ 1);
        prB[1] = mapa_peer(smem_u32(&hbuf[1][bA * HST + pgB]), rank ^ 1);
    }

    // ---- gi staging setup: thread r<240 owns one (gate,unit) row of 8 halves ----
    const __half* gib = gi + (size_t)dir * Mrows * G3;
    const bool is_ld = (tid < GROWS);
    const int rgate = tid / 80;                 // 0..2 (for tid<240)
    const int runit = tid - rgate * 80;         // 0..79
    const int rn = rgate * 160 + rank * 80 + runit;   // gi row n
    const __half* srcRow = gib + (size_t)rn * 256 + b0;
    const uint32_t gis_base = smem_u32(&gis[0][0]);
    const uint32_t dstRow = gis_base + (uint32_t)tid * 16;

    for (int i = tid; i < 2 * HBUFN; i += 512) (&hbuf[0][0])[i] = 0.f;

    // prologue: stage gi for s=0 into slot 0
    {
        const int t0 = dir ? (Tt - 1) : 0;
        if (is_ld) cp_async16(dstRow, srcRow + (size_t)t0 * G3 * 256);
        cp_commit();
    }

    __syncthreads();
    CLUSTER_SYNC();

    float hA = 0.f, hB = 0.f;
    int cur = 0;

    for (int s = 0; s < Tt; s++) {
        // stage gi for s+1 into slot cur^1
        if (s + 1 < Tt) {
            const int tn = dir ? (Tt - 2 - s) : (s + 1);
            if (is_ld) cp_async16(dstRow + (cur ^ 1) * (GROWS * 16),
                                  srcRow + (size_t)tn * G3 * 256);
        }
        cp_commit();

        if (is_mma) {
            float accA[4] = {0.f, 0.f, 0.f, 0.f};
            float accB4[4] = {0.f, 0.f, 0.f, 0.f};
            const float* hc = hbuf[cur];
            const int hbase = grp * HST;

            // phase L: own-half k (no peer dependency)
#pragma unroll
            for (int j = 0; j < 10; j += 2) {
                float2 v0 = *(const float2*)&hc[hbase + (ktL + j) * 8 + tq * 2];
                mma_tf32(accA, &wreg[j * 4], (const uint32_t*)&v0);
                float2 v1 = *(const float2*)&hc[hbase + (ktL + j + 1) * 8 + tq * 2];
                mma_tf32(accB4, &wreg[(j + 1) * 4], (const uint32_t*)&v1);
            }

            if (s > 0) {
                mbar_wait_parity((s & 1) ? mbar1 : mbar0, ((s - 1) >> 1) & 1);
            }

            // phase R: peer-half k
#pragma unroll
            for (int j = 0; j < 10; j += 2) {
                float2 v0 = *(const float2*)&hc[hbase + (ktR + j) * 8 + tq * 2];
                mma_tf32(accA, &wreg[40 + j * 4], (const uint32_t*)&v0);
                float2 v1 = *(const float2*)&hc[hbase + (ktR + j + 1) * 8 + tq * 2];
                mma_tf32(accB4, &wreg[40 + (j + 1) * 4], (const uint32_t*)&v1);
            }

            const int lr = wid * 16;
            *(float2*)&gh[(lr + grp) * 8 + 2 * tq] =
                make_float2(accA[0] + accB4[0], accA[1] + accB4[1]);
            *(float2*)&gh[(lr + 8 + grp) * 8 + 2 * tq] =
                make_float2(accA[2] + accB4[2], accA[3] + accB4[3]);
        }
        cp_wait1();
        __syncthreads();

        const int t = dir ? (Tt - 1 - s) : s;
        const int nxt = cur ^ 1;
        const __half* gs = &gis[cur][0];
        {
            float gir = __half2float(gs[(0 * 80 + uA) * 8 + bA]);
            float giz = __half2float(gs[(1 * 80 + uA) * 8 + bA]);
            float gin = __half2float(gs[(2 * 80 + uA) * 8 + bA]);
            float r = fmaf(tanh_ap(0.5f * (gir + gh[uA * 8 + bA] + bhrA)), 0.5f, 0.5f);
            float z = fmaf(tanh_ap(0.5f * (giz + gh[(80 + uA) * 8 + bA] + bhzA)), 0.5f, 0.5f);
            float n = tanh_ap(gin + r * (gh[(160 + uA) * 8 + bA] + bhnA));
            hA = fmaf(z, hA - n, n);
            uint32_t htf = f2tf32(hA);
            *(uint32_t*)&hbuf[nxt][bA * HST + pgA] = htf;
            st_cluster_u32(prA[nxt], htf);
            if (layer == 0) {
                ((__half*)yout)[((size_t)t * 320 + dir * Hh + gA) * 256 + b0 + bA] =
                    __float2half(hA);
            }
        }
        if (hasB) {
            float gir = __half2float(gs[(0 * 80 + uB) * 8 + bA]);
            float giz = __half2float(gs[(1 * 80 + uB) * 8 + bA]);
            float gin = __half2float(gs[(2 * 80 + uB) * 8 + bA]);
            float r = fmaf(tanh_ap(0.5f * (gir + gh[uB * 8 + bA] + bhrB)), 0.5f, 0.5f);
            float z = fmaf(tanh_ap(0.5f * (giz + gh[(80 + uB) * 8 + bA] + bhzB)), 0.5f, 0.5f);
            float n = tanh_ap(gin + r * (gh[(160 + uB) * 8 + bA] + bhnB));
            hB = fmaf(z, hB - n, n);
            uint32_t htf = f2tf32(hB);
            *(uint32_t*)&hbuf[nxt][bA * HST + pgB] = htf;
            st_cluster_u32(prB[nxt], htf);
            if (layer == 0) {
                ((__half*)yout)[((size_t)t * 320 + dir * Hh + gB) * 256 + b0 + bA] =
                    __float2half(hB);
            }
        }
        __syncthreads();   // all peer stores issued before the release below
        if (tid == 0) {
            mbar_arrive_peer((nxt & 1) ? pbar1 : pbar0);
        }
        cur = nxt;
    }

    if (layer == 1) {
        float* hf = (float*)yout;
        hf[((size_t)(dir * Bb) + b0 + bA) * Hh + gA] = hA;
        if (hasB) hf[((size_t)(dir * Bb) + b0 + bA) * Hh + gB] = hB;
    }
    CLUSTER_SYNC();   // no CTA exits while peer stores into its smem may be in flight
}

// ---------------------------------------------------------------------------
// K5: head
// ---------------------------------------------------------------------------
__global__ __launch_bounds__(128)
void head_kernel(const float* __restrict__ hfin,
                 const float* __restrict__ fc1w, const float* __restrict__ fc1b,
                 const float* __restrict__ fc2w, const float* __restrict__ fc2b,
                 float* __restrict__ out) {
    const int b = blockIdx.x;
    const int j = threadIdx.x;
    __shared__ float hv[320];
    __shared__ float red[4];

    for (int k = j; k < Hh; k += 128) {
        hv[k]      = hfin[(size_t)b * Hh + k];
        hv[Hh + k] = hfin[(size_t)Bb * Hh + (size_t)b * Hh + k];
    }
    __syncthreads();

    float acc = fc1b[j];
    const float* wr = fc1w + (size_t)j * 320;
#pragma unroll 8
    for (int k = 0; k < 320; k++) acc += wr[k] * hv[k];
    float v = fmaxf(acc, 0.f) * fc2w[j];

#pragma unroll
    for (int o = 16; o > 0; o >>= 1) v += __shfl_down_sync(0xffffffffu, v, o);
    if ((j & 31) == 0) red[j >> 5] = v;
    __syncthreads();
    if (j == 0) out[b] = red[0] + red[1] + red[2] + red[3] + fc2b[0];
}

// ---------------------------------------------------------------------------
// kernel_launch — sequential pipeline (graph-capturable, profiler-safe)
// ---------------------------------------------------------------------------
extern "C" void kernel_launch(void* const* d_in, const int* in_sizes, int n_in,
                              void* d_out, int out_size) {
    const int*   x        = (const int*)  d_in[0];
    const float* emb      = (const float*)d_in[1];
    const float* Wih_l0f  = (const float*)d_in[2];
    const float* Whh_l0f  = (const float*)d_in[3];
    const float* bih_l0f  = (const float*)d_in[4];
    const float* bhh_l0f  = (const float*)d_in[5];
    const float* Wih_l0b  = (const float*)d_in[6];
    const float* Whh_l0b  = (const float*)d_in[7];
    const float* bih_l0b  = (const float*)d_in[8];
    const float* bhh_l0b  = (const float*)d_in[9];
    const float* Wih_l1f  = (const float*)d_in[10];
    const float* Whh_l1f  = (const float*)d_in[11];
    const float* bih_l1f  = (const float*)d_in[12];
    const float* bhh_l1f  = (const float*)d_in[13];
    const float* Wih_l1b  = (const float*)d_in[14];
    const float* Whh_l1b  = (const float*)d_in[15];
    const float* bih_l1b  = (const float*)d_in[16];
    const float* bhh_l1b  = (const float*)d_in[17];
    const float* fc1_w    = (const float*)d_in[18];
    const float* fc1_b    = (const float*)d_in[19];
    const float* fc2_w    = (const float*)d_in[20];
    const float* fc2_b    = (const float*)d_in[21];
    float* out = (float*)d_out;

    __half *gi0, *gi1, *y0;
    float *hfin;
    cudaGetSymbolAddress((void**)&gi0,  g_gi0);
    cudaGetSymbolAddress((void**)&gi1,  g_gi1);
    cudaGetSymbolAddress((void**)&y0,   g_y0);
    cudaGetSymbolAddress((void**)&hfin, g_hfin);

    {
        dim3 grid(Mrows / 128, G3 / 96, 2);
        gates_mma_kernel<128, true><<<grid, 256>>>(emb, x, Wih_l0f, Wih_l0b,
                                                   bih_l0f, bih_l0b, gi0);
    }

    scan_mma_kernel<<<dim3(64, 2), 512>>>(gi0, Whh_l0f, Whh_l0b,
                                          bhh_l0f, bhh_l0b, y0, 0);

    {
        dim3 grid(Mrows / 128, G3 / 96, 2);
        gates_mma_kernel<320, false><<<grid, 256>>>(y0, nullptr, Wih_l1f, Wih_l1b,
                                                    bih_l1f, bih_l1b, gi1);
    }

    scan_mma_kernel<<<dim3(64, 2), 512>>>(gi1, Whh_l1f, Whh_l1b,
                                          bhh_l1f, bhh_l1b, hfin, 1);

    head_kernel<<<Bb, 128>>>(hfin, fc1_w, fc1_b, fc2_w, fc2_b, out);
}

// round 11
// speedup vs baseline: 1.0251x; 1.0251x over previous
#include <cuda_runtime.h>
#include <cuda_fp16.h>
#include <math.h>
#include <stdint.h>

// ---------------------------------------------------------------------------
// TextGRUClassifier: 2-layer bidir GRU (B=256,T=512,E=128,H=160) + FC head
// R11: GEMMs/gi/y0 reverted to R7 (fp32, known-good). Scan rebuilt cluster-free:
//   m16n8k16 f16 mma (same 10-bit mantissa as tf32), FULL Whh in registers of a
//   single CTA (15 mma warps x 80 half2 regs), single fp16 h buffer in smem with
//   k-permuted layout (KST=176 -> conflict-free LDS.64 B-fragments). No DSMEM,
//   no mbarrier handshake: 2 bar.sync per step.
// ---------------------------------------------------------------------------

#define Tt 512
#define Bb 256
#define Hh 160
#define G3 480
#define Mrows (Tt*Bb)     // 131072

// ---- scratch ----
static __device__ float g_gi0[(size_t)2 * Mrows * G3];   // [dir][t][n=480][b=256]
static __device__ float g_gi1[(size_t)2 * Mrows * G3];
static __device__ float g_y0[(size_t)Mrows * 320];       // [t][n=320][b=256]
static __device__ float g_hfin[2 * Bb * Hh];             // [dir][b][g]

// ---- helpers ----
__device__ __forceinline__ float tanh_ap(float x) {
    float r;
    asm("tanh.approx.f32 %0, %1;" : "=f"(r) : "f"(x));
    return r;
}
__device__ __forceinline__ uint32_t f2tf32(float x) {
    uint32_t r;
    asm("cvt.rna.tf32.f32 %0, %1;" : "=r"(r) : "f"(x));
    return r;
}
__device__ __forceinline__ uint32_t packh2(float x, float y) {
    __half2 h = __floats2half2_rn(x, y);
    return *(uint32_t*)&h;
}
__device__ __forceinline__ void mma_tf32(float* d, const uint32_t* a, const uint32_t* b) {
    asm volatile(
        "mma.sync.aligned.m16n8k8.row.col.f32.tf32.tf32.f32 "
        "{%0,%1,%2,%3}, {%4,%5,%6,%7}, {%8,%9}, {%0,%1,%2,%3};"
        : "+f"(d[0]), "+f"(d[1]), "+f"(d[2]), "+f"(d[3])
        : "r"(a[0]), "r"(a[1]), "r"(a[2]), "r"(a[3]), "r"(b[0]), "r"(b[1]));
}
__device__ __forceinline__ void mma_f16(float* d, const uint32_t* a, uint32_t b0, uint32_t b1) {
    asm volatile(
        "mma.sync.aligned.m16n8k16.row.col.f32.f16.f16.f32 "
        "{%0,%1,%2,%3}, {%4,%5,%6,%7}, {%8,%9}, {%0,%1,%2,%3};"
        : "+f"(d[0]), "+f"(d[1]), "+f"(d[2]), "+f"(d[3])
        : "r"(a[0]), "r"(a[1]), "r"(a[2]), "r"(a[3]), "r"(b0), "r"(b1));
}
__device__ __forceinline__ uint32_t smem_u32(const void* p) {
    uint32_t a;
    asm("{ .reg .u64 t; cvta.to.shared.u64 t, %1; cvt.u32.u64 %0, t; }" : "=r"(a) : "l"(p));
    return a;
}
__device__ __forceinline__ void cp_async16(uint32_t dst, const void* src) {
    asm volatile("cp.async.ca.shared.global [%0], [%1], 16;" :: "r"(dst), "l"(src) : "memory");
}
__device__ __forceinline__ void cp_commit() {
    asm volatile("cp.async.commit_group;" ::: "memory");
}
__device__ __forceinline__ void cp_wait1() {
    asm volatile("cp.async.wait_group 1;" ::: "memory");
}
// k-permutation slot within a 16-group: order [0,1,8,9, 2,3,10,11, 4,5,12,13, 6,7,14,15]
__device__ __forceinline__ int hslot(int j) {
    return (j < 8) ? ((j >> 1) * 4 + (j & 1)) : (((j - 8) >> 1) * 4 + 2 + (j & 1));
}

// ---------------------------------------------------------------------------
// K1/K3: gates GEMM on tf32 tensor cores (R7 version, fp32 in/out).
//   out layout: [dir][t][n=480][b=256].
// ---------------------------------------------------------------------------
#define ALD 36
#define MLD 136

template <int KDIM, bool GATHER>
__global__ __launch_bounds__(256, 2)
void gates_mma_kernel(const float* __restrict__ A, const int* __restrict__ xids,
                      const float* __restrict__ Wf, const float* __restrict__ Wb,
                      const float* __restrict__ bf, const float* __restrict__ bb,
                      float* __restrict__ out) {
    const int m0 = blockIdx.x * 128;
    const int n0 = blockIdx.y * 96;
    const int dir = blockIdx.z;
    const float* W = dir ? Wb : Wf;
    const float* bias = dir ? bb : bf;
    float* outp = out + (size_t)dir * Mrows * G3;

    __shared__ float As[128 * ALD];
    __shared__ float Bs[96 * ALD];
    __shared__ int rid[128];

    const int tid = threadIdx.x;
    if (GATHER) {
        if (tid < 128) {
            int m = m0 + tid;
            rid[tid] = xids[(m & 255) * Tt + (m >> 8)];
        }
        __syncthreads();
    }

    const int lane = tid & 31, wid = tid >> 5;
    const int grp = lane >> 2, tq = lane & 3;
    const int m_off = (wid >> 1) * 32;
    const int n_off = (wid & 1) * 48;

    float acc[2][6][4];
#pragma unroll
    for (int i = 0; i < 2; i++)
#pragma unroll
        for (int j = 0; j < 6; j++)
#pragma unroll
            for (int c = 0; c < 4; c++) acc[i][j][c] = 0.f;

    const int rA = tid >> 3;
    const int cA = tid & 7;
    const float* arow[4];
    if (GATHER) {
#pragma unroll
        for (int u = 0; u < 4; u++) arow[u] = A + (size_t)rid[rA + u * 32] * KDIM;
    }
    const float* Abase = GATHER ? nullptr
                        : A + ((size_t)(m0 >> 8) * KDIM) * 256 + (m0 & 255);

    const float* brow[3];
#pragma unroll
    for (int u = 0; u < 3; u++) brow[u] = W + (size_t)(n0 + rA + u * 32) * KDIM;

    const int KT = KDIM / 32;
    float4 aR[4], bR[3];

    if (GATHER) {
#pragma unroll
        for (int u = 0; u < 4; u++) aR[u] = *(const float4*)(arow[u] + cA * 4);
    } else {
#pragma unroll
        for (int u = 0; u < 4; u++) {
            int idx = u * 256 + tid;
            int k = idx >> 5, m4 = (idx & 31) * 4;
            aR[u] = *(const float4*)(Abase + (size_t)k * 256 + m4);
        }
    }
#pragma unroll
    for (int u = 0; u < 3; u++) bR[u] = *(const float4*)(brow[u] + cA * 4);

    for (int kt = 0; kt < KT; kt++) {
        __syncthreads();
        if (GATHER) {
#pragma unroll
            for (int u = 0; u < 4; u++) {
                float4 v = aR[u];
                float4 w4 = make_float4(__uint_as_float(f2tf32(v.x)), __uint_as_float(f2tf32(v.y)),
                                        __uint_as_float(f2tf32(v.z)), __uint_as_float(f2tf32(v.w)));
                *(float4*)&As[(rA + u * 32) * ALD + cA * 4] = w4;
            }
        } else {
#pragma unroll
            for (int u = 0; u < 4; u++) {
                int idx = u * 256 + tid;
                int k = idx >> 5, m4 = (idx & 31) * 4;
                float4 v = aR[u];
                float4 w4 = make_float4(__uint_as_float(f2tf32(v.x)), __uint_as_float(f2tf32(v.y)),
                                        __uint_as_float(f2tf32(v.z)), __uint_as_float(f2tf32(v.w)));
                *(float4*)&As[k * MLD + m4] = w4;
            }
        }
#pragma unroll
        for (int u = 0; u < 3; u++) {
            float4 v = bR[u];
            float4 w4 = make_float4(__uint_as_float(f2tf32(v.x)), __uint_as_float(f2tf32(v.y)),
                                    __uint_as_float(f2tf32(v.z)), __uint_as_float(f2tf32(v.w)));
            *(float4*)&Bs[(rA + u * 32) * ALD + cA * 4] = w4;
        }
        __syncthreads();

        if (kt + 1 < KT) {
            int ko = (kt + 1) * 32;
            if (GATHER) {
#pragma unroll
                for (int u = 0; u < 4; u++) aR[u] = *(const float4*)(arow[u] + ko + cA * 4);
            } else {
#pragma unroll
                for (int u = 0; u < 4; u++) {
                    int idx = u * 256 + tid;
                    int k = idx >> 5, m4 = (idx & 31) * 4;
                    aR[u] = *(const float4*)(Abase + (size_t)(ko + k) * 256 + m4);
                }
            }
#pragma unroll
            for (int u = 0; u < 3; u++) bR[u] = *(const float4*)(brow[u] + ko + cA * 4);
        }

#pragma unroll
        for (int kc = 0; kc < 4; kc++) {
            const int kk0 = kc * 8;
            uint32_t af[2][4];
            if (GATHER) {
#pragma unroll
                for (int i = 0; i < 2; i++) {
                    int rm = m_off + i * 16;
                    af[i][0] = __float_as_uint(As[(rm + grp) * ALD + kk0 + tq]);
                    af[i][1] = __float_as_uint(As[(rm + 8 + grp) * ALD + kk0 + tq]);
                    af[i][2] = __float_as_uint(As[(rm + grp) * ALD + kk0 + tq + 4]);
                    af[i][3] = __float_as_uint(As[(rm + 8 + grp) * ALD + kk0 + tq + 4]);
                }
            } else {
#pragma unroll
                for (int i = 0; i < 2; i++) {
                    int rm = m_off + i * 16;
                    af[i][0] = __float_as_uint(As[(kk0 + tq) * MLD + rm + grp]);
                    af[i][1] = __float_as_uint(As[(kk0 + tq) * MLD + rm + 8 + grp]);
                    af[i][2] = __float_as_uint(As[(kk0 + tq + 4) * MLD + rm + grp]);
                    af[i][3] = __float_as_uint(As[(kk0 + tq + 4) * MLD + rm + 8 + grp]);
                }
            }
            uint32_t bfr[6][2];
#pragma unroll
            for (int j = 0; j < 6; j++) {
                int nb = n_off + j * 8;
                bfr[j][0] = __float_as_uint(Bs[(nb + grp) * ALD + kk0 + tq]);
                bfr[j][1] = __float_as_uint(Bs[(nb + grp) * ALD + kk0 + tq + 4]);
            }
#pragma unroll
            for (int i = 0; i < 2; i++)
#pragma unroll
                for (int j = 0; j < 6; j++) mma_tf32(acc[i][j], af[i], bfr[j]);
        }
    }

    {
        const int t_t = m0 >> 8;
        const int bb = m0 & 255;
        float* ob = outp + (size_t)t_t * G3 * 256 + bb;
#pragma unroll
        for (int j = 0; j < 6; j++) {
            int col = n0 + n_off + j * 8 + 2 * tq;
            float b0v = bias[col], b1v = bias[col + 1];
#pragma unroll
            for (int i = 0; i < 2; i++) {
                int ml = m_off + i * 16 + grp;
                ob[(size_t)col * 256 + ml]           = acc[i][j][0] + b0v;
                ob[(size_t)(col + 1) * 256 + ml]     = acc[i][j][1] + b1v;
                ob[(size_t)col * 256 + ml + 8]       = acc[i][j][2] + b0v;
                ob[(size_t)(col + 1) * 256 + ml + 8] = acc[i][j][3] + b1v;
            }
        }
    }
}

// ---------------------------------------------------------------------------
// K2/K4: cluster-free GRU scan on f16 tensor cores. grid=(32,2), 512 threads.
//   15 mma warps, warp wid owns gate rows [wid*32, wid*32+32) = two m16 tiles,
//   full k=160 of Whh in 80 half2 registers. h: single fp16 smem buffer,
//   [b=8][KST=176] with k-permuted 16-groups -> one LDS.64 = {b0,b1} fragment.
//   Combine: 1280 items = 3 per thread (A,B always; C for tid<256).
// ---------------------------------------------------------------------------
#define KST 176                   // halves per hbuf row (conflict-free: 88%32=24)

__global__ __launch_bounds__(512, 1)
void scan_mma_kernel(const float* __restrict__ gi,
                     const float* __restrict__ whhF, const float* __restrict__ whhB,
                     const float* __restrict__ bhf, const float* __restrict__ bhb,
                     float* __restrict__ yout, int layer) {
    __shared__ __align__(16) __half hbuf[8 * KST];    // [b][perm(k)]
    __shared__ float gh[G3 * 8];                      // [whh_row][b]
    __shared__ __align__(16) float gis[2][G3 * 8];    // staged gi [row][b]

    const int dir = blockIdx.y;
    const int b0 = blockIdx.x * 8;
    const int tid = threadIdx.x;
    const int wid = tid >> 5, lane = tid & 31;
    const int grp = lane >> 2, tq = lane & 3;

    // ---- preload FULL Whh as f16 A-fragments (m16n8k16) ----
    const bool is_mma = (wid < 15);
    uint32_t w0[40], w1[40];     // [kt*4 + q], two m-tiles
    if (is_mma) {
        const float* W = dir ? whhB : whhF;
        const int r0 = wid * 32 + grp;          // tile0 rows r0, r0+8
        const int r1 = wid * 32 + 16 + grp;     // tile1 rows r1, r1+8
#pragma unroll
        for (int kt = 0; kt < 10; kt++) {
            const int k0 = kt * 16 + 2 * tq;
            w0[kt * 4 + 0] = packh2(W[(size_t)r0 * Hh + k0],     W[(size_t)r0 * Hh + k0 + 1]);
            w0[kt * 4 + 1] = packh2(W[(size_t)(r0 + 8) * Hh + k0], W[(size_t)(r0 + 8) * Hh + k0 + 1]);
            w0[kt * 4 + 2] = packh2(W[(size_t)r0 * Hh + k0 + 8], W[(size_t)r0 * Hh + k0 + 9]);
            w0[kt * 4 + 3] = packh2(W[(size_t)(r0 + 8) * Hh + k0 + 8], W[(size_t)(r0 + 8) * Hh + k0 + 9]);
            w1[kt * 4 + 0] = packh2(W[(size_t)r1 * Hh + k0],     W[(size_t)r1 * Hh + k0 + 1]);
            w1[kt * 4 + 1] = packh2(W[(size_t)(r1 + 8) * Hh + k0], W[(size_t)(r1 + 8) * Hh + k0 + 1]);
            w1[kt * 4 + 2] = packh2(W[(size_t)r1 * Hh + k0 + 8], W[(size_t)r1 * Hh + k0 + 9]);
            w1[kt * 4 + 3] = packh2(W[(size_t)(r1 + 8) * Hh + k0 + 8], W[(size_t)(r1 + 8) * Hh + k0 + 9]);
        }
    }

    // ---- combine-item setup: A (all), B (all), C (tid<256) ----
    const int uA = tid >> 3, bA = tid & 7;
    const int uB = uA + 64;
    const int uC = uA + 128;                    // valid if tid < 256
    const bool hasC = (tid < 256);
    const int pgA = (uA >> 4) * 16 + hslot(uA & 15);
    const int pgB = (uB >> 4) * 16 + hslot(uB & 15);
    const int pgC = (uC >> 4) * 16 + hslot(uC & 15);
    const float* bh = dir ? bhb : bhf;
    const float bhrA = bh[uA], bhzA = bh[Hh + uA], bhnA = bh[2 * Hh + uA];
    const float bhrB = bh[uB], bhzB = bh[Hh + uB], bhnB = bh[2 * Hh + uB];
    float bhrC = 0.f, bhzC = 0.f, bhnC = 0.f;
    if (hasC) { bhrC = bh[uC]; bhzC = bh[Hh + uC]; bhnC = bh[2 * Hh + uC]; }

    // ---- gi staging: thread r<480 owns whh-row r (8 floats = 2 x 16B) ----
    const float* gib = gi + (size_t)dir * Mrows * G3;
    const bool is_ld = (tid < G3);
    const float* srcRow = gib + (size_t)tid * 256 + b0;
    const uint32_t gis_base = smem_u32(&gis[0][0]);
    const uint32_t dstRow = gis_base + (uint32_t)tid * 32;
    const uint32_t slotBytes = G3 * 8 * 4;      // 15360

    for (int i = tid; i < 8 * KST; i += 512) hbuf[i] = __float2half(0.f);

    // prologue: stage gi for s=0 into slot 0
    {
        const int t0 = dir ? (Tt - 1) : 0;
        const float* s = srcRow + (size_t)t0 * G3 * 256;
        if (is_ld) {
            cp_async16(dstRow, s);
            cp_async16(dstRow + 16, s + 4);
        }
        cp_commit();
    }
    __syncthreads();

    float hA = 0.f, hB = 0.f, hC = 0.f;
    int cur = 0;

    for (int s = 0; s < Tt; s++) {
        // stage gi for s+1
        if (s + 1 < Tt) {
            const int tn = dir ? (Tt - 2 - s) : (s + 1);
            const float* sp = srcRow + (size_t)tn * G3 * 256;
            if (is_ld) {
                cp_async16(dstRow + (cur ^ 1) * slotBytes, sp);
                cp_async16(dstRow + (cur ^ 1) * slotBytes + 16, sp + 4);
            }
        }
        cp_commit();

        if (is_mma) {
            float a0e[4] = {0,0,0,0}, a0o[4] = {0,0,0,0};
            float a1e[4] = {0,0,0,0}, a1o[4] = {0,0,0,0};
            const __half* hb = &hbuf[grp * KST + tq * 4];
#pragma unroll
            for (int kt = 0; kt < 10; kt += 2) {
                uint2 bv0 = *(const uint2*)(hb + kt * 16);
                mma_f16(a0e, &w0[kt * 4], bv0.x, bv0.y);
                mma_f16(a1e, &w1[kt * 4], bv0.x, bv0.y);
                uint2 bv1 = *(const uint2*)(hb + (kt + 1) * 16);
                mma_f16(a0o, &w0[(kt + 1) * 4], bv1.x, bv1.y);
                mma_f16(a1o, &w1[(kt + 1) * 4], bv1.x, bv1.y);
            }
            const int lr = wid * 32;
            *(float2*)&gh[(lr + grp) * 8 + 2 * tq] =
                make_float2(a0e[0] + a0o[0], a0e[1] + a0o[1]);
            *(float2*)&gh[(lr + 8 + grp) * 8 + 2 * tq] =
                make_float2(a0e[2] + a0o[2], a0e[3] + a0o[3]);
            *(float2*)&gh[(lr + 16 + grp) * 8 + 2 * tq] =
                make_float2(a1e[0] + a1o[0], a1e[1] + a1o[1]);
            *(float2*)&gh[(lr + 24 + grp) * 8 + 2 * tq] =
                make_float2(a1e[2] + a1o[2], a1e[3] + a1o[3]);
        }
        cp_wait1();
        __syncthreads();   // gh ready; hbuf reads done; gi[cur] staged

        const int t = dir ? (Tt - 1 - s) : s;
        const float* gs = &gis[cur][0];
        {
            float gir = gs[uA * 8 + bA], giz = gs[(Hh + uA) * 8 + bA], gin = gs[(2 * Hh + uA) * 8 + bA];
            float r = fmaf(tanh_ap(0.5f * (gir + gh[uA * 8 + bA] + bhrA)), 0.5f, 0.5f);
            float z = fmaf(tanh_ap(0.5f * (giz + gh[(Hh + uA) * 8 + bA] + bhzA)), 0.5f, 0.5f);
            float n = tanh_ap(gin + r * (gh[(2 * Hh + uA) * 8 + bA] + bhnA));
            hA = fmaf(z, hA - n, n);
            hbuf[bA * KST + pgA] = __float2half(hA);
            if (layer == 0)
                yout[((size_t)t * 320 + dir * Hh + uA) * 256 + b0 + bA] = hA;
        }
        {
            float gir = gs[uB * 8 + bA], giz = gs[(Hh + uB) * 8 + bA], gin = gs[(2 * Hh + uB) * 8 + bA];
            float r = fmaf(tanh_ap(0.5f * (gir + gh[uB * 8 + bA] + bhrB)), 0.5f, 0.5f);
            float z = fmaf(tanh_ap(0.5f * (giz + gh[(Hh + uB) * 8 + bA] + bhzB)), 0.5f, 0.5f);
            float n = tanh_ap(gin + r * (gh[(2 * Hh + uB) * 8 + bA] + bhnB));
            hB = fmaf(z, hB - n, n);
            hbuf[bA * KST + pgB] = __float2half(hB);
            if (layer == 0)
                yout[((size_t)t * 320 + dir * Hh + uB) * 256 + b0 + bA] = hB;
        }
        if (hasC) {
            float gir = gs[uC * 8 + bA], giz = gs[(Hh + uC) * 8 + bA], gin = gs[(2 * Hh + uC) * 8 + bA];
            float r = fmaf(tanh_ap(0.5f * (gir + gh[uC * 8 + bA] + bhrC)), 0.5f, 0.5f);
            float z = fmaf(tanh_ap(0.5f * (giz + gh[(Hh + uC) * 8 + bA] + bhzC)), 0.5f, 0.5f);
            float n = tanh_ap(gin + r * (gh[(2 * Hh + uC) * 8 + bA] + bhnC));
            hC = fmaf(z, hC - n, n);
            hbuf[bA * KST + pgC] = __float2half(hC);
            if (layer == 0)
                yout[((size_t)t * 320 + dir * Hh + uC) * 256 + b0 + bA] = hC;
        }
        __syncthreads();   // h writes visible before next step's mma reads
        cur ^= 1;
    }

    if (layer == 1) {
        yout[((size_t)(dir * Bb) + b0 + bA) * Hh + uA] = hA;
        yout[((size_t)(dir * Bb) + b0 + bA) * Hh + uB] = hB;
        if (hasC) yout[((size_t)(dir * Bb) + b0 + bA) * Hh + uC] = hC;
    }
}

// ---------------------------------------------------------------------------
// K5: head
// ---------------------------------------------------------------------------
__global__ __launch_bounds__(128)
void head_kernel(const float* __restrict__ hfin,
                 const float* __restrict__ fc1w, const float* __restrict__ fc1b,
                 const float* __restrict__ fc2w, const float* __restrict__ fc2b,
                 float* __restrict__ out) {
    const int b = blockIdx.x;
    const int j = threadIdx.x;
    __shared__ float hv[320];
    __shared__ float red[4];

    for (int k = j; k < Hh; k += 128) {
        hv[k]      = hfin[(size_t)b * Hh + k];
        hv[Hh + k] = hfin[(size_t)Bb * Hh + (size_t)b * Hh + k];
    }
    __syncthreads();

    float acc = fc1b[j];
    const float* wr = fc1w + (size_t)j * 320;
#pragma unroll 8
    for (int k = 0; k < 320; k++) acc += wr[k] * hv[k];
    float v = fmaxf(acc, 0.f) * fc2w[j];

#pragma unroll
    for (int o = 16; o > 0; o >>= 1) v += __shfl_down_sync(0xffffffffu, v, o);
    if ((j & 31) == 0) red[j >> 5] = v;
    __syncthreads();
    if (j == 0) out[b] = red[0] + red[1] + red[2] + red[3] + fc2b[0];
}

// ---------------------------------------------------------------------------
// kernel_launch — sequential pipeline (graph-capturable, profiler-safe)
// ---------------------------------------------------------------------------
extern "C" void kernel_launch(void* const* d_in, const int* in_sizes, int n_in,
                              void* d_out, int out_size) {
    const int*   x        = (const int*)  d_in[0];
    const float* emb      = (const float*)d_in[1];
    const float* Wih_l0f  = (const float*)d_in[2];
    const float* Whh_l0f  = (const float*)d_in[3];
    const float* bih_l0f  = (const float*)d_in[4];
    const float* bhh_l0f  = (const float*)d_in[5];
    const float* Wih_l0b  = (const float*)d_in[6];
    const float* Whh_l0b  = (const float*)d_in[7];
    const float* bih_l0b  = (const float*)d_in[8];
    const float* bhh_l0b  = (const float*)d_in[9];
    const float* Wih_l1f  = (const float*)d_in[10];
    const float* Whh_l1f  = (const float*)d_in[11];
    const float* bih_l1f  = (const float*)d_in[12];
    const float* bhh_l1f  = (const float*)d_in[13];
    const float* Wih_l1b  = (const float*)d_in[14];
    const float* Whh_l1b  = (const float*)d_in[15];
    const float* bih_l1b  = (const float*)d_in[16];
    const float* bhh_l1b  = (const float*)d_in[17];
    const float* fc1_w    = (const float*)d_in[18];
    const float* fc1_b    = (const float*)d_in[19];
    const float* fc2_w    = (const float*)d_in[20];
    const float* fc2_b    = (const float*)d_in[21];
    float* out = (float*)d_out;

    float *gi0, *gi1, *y0, *hfin;
    cudaGetSymbolAddress((void**)&gi0,  g_gi0);
    cudaGetSymbolAddress((void**)&gi1,  g_gi1);
    cudaGetSymbolAddress((void**)&y0,   g_y0);
    cudaGetSymbolAddress((void**)&hfin, g_hfin);

    {
        dim3 grid(Mrows / 128, G3 / 96, 2);
        gates_mma_kernel<128, true><<<grid, 256>>>(emb, x, Wih_l0f, Wih_l0b,
                                                   bih_l0f, bih_l0b, gi0);
    }

    scan_mma_kernel<<<dim3(32, 2), 512>>>(gi0, Whh_l0f, Whh_l0b,
                                          bhh_l0f, bhh_l0b, y0, 0);

    {
        dim3 grid(Mrows / 128, G3 / 96, 2);
        gates_mma_kernel<320, false><<<grid, 256>>>(y0, nullptr, Wih_l1f, Wih_l1b,
                                                    bih_l1f, bih_l1b, gi1);
    }

    scan_mma_kernel<<<dim3(32, 2), 512>>>(gi1, Whh_l1f, Whh_l1b,
                                          bhh_l1f, bhh_l1b, hfin, 1);

    head_kernel<<<Bb, 128>>>(hfin, fc1_w, fc1_b, fc2_w, fc2_b, out);
}

// round 12
// speedup vs baseline: 1.0785x; 1.0521x over previous
#include <cuda_runtime.h>
#include <cuda_fp16.h>
#include <math.h>
#include <stdint.h>

// ---------------------------------------------------------------------------
// TextGRUClassifier: 2-layer bidir GRU (B=256,T=512,E=128,H=160) + FC head
// R12 = measured-best pieces only:
//   - GEMMs: R7 code verbatim (fp32 A/B, float4 staging) with ONE change:
//     epilogue writes gi as fp16 (halves the dominant store stream).
//   - Scan: R10 cluster scan verbatim (fp16 gi staging, k-split mma around the
//     mbar handshake, tanh.approx) but y0/hfin stay fp32 (GEMM1 A-path intact).
// ---------------------------------------------------------------------------

#define Tt 512
#define Bb 256
#define Hh 160
#define G3 480
#define Mrows (Tt*Bb)     // 131072

// ---- scratch ----
static __device__ __half g_gi0[(size_t)2 * Mrows * G3];  // [dir][t][n=480][b=256]
static __device__ __half g_gi1[(size_t)2 * Mrows * G3];
static __device__ float  g_y0[(size_t)Mrows * 320];      // [t][n=320][b=256] fp32
static __device__ float  g_hfin[2 * Bb * Hh];            // [dir][b][g]

// ---- helpers ----
__device__ __forceinline__ float tanh_ap(float x) {
    float r;
    asm("tanh.approx.f32 %0, %1;" : "=f"(r) : "f"(x));
    return r;
}
__device__ __forceinline__ uint32_t f2tf32(float x) {
    uint32_t r;
    asm("cvt.rna.tf32.f32 %0, %1;" : "=r"(r) : "f"(x));
    return r;
}
__device__ __forceinline__ void mma_tf32(float* d, const uint32_t* a, const uint32_t* b) {
    asm volatile(
        "mma.sync.aligned.m16n8k8.row.col.f32.tf32.tf32.f32 "
        "{%0,%1,%2,%3}, {%4,%5,%6,%7}, {%8,%9}, {%0,%1,%2,%3};"
        : "+f"(d[0]), "+f"(d[1]), "+f"(d[2]), "+f"(d[3])
        : "r"(a[0]), "r"(a[1]), "r"(a[2]), "r"(a[3]), "r"(b[0]), "r"(b[1]));
}
__device__ __forceinline__ uint32_t smem_u32(const void* p) {
    uint32_t a;
    asm("{ .reg .u64 t; cvta.to.shared.u64 t, %1; cvt.u32.u64 %0, t; }" : "=r"(a) : "l"(p));
    return a;
}
__device__ __forceinline__ uint32_t mapa_peer(uint32_t addr, uint32_t rank) {
    uint32_t r;
    asm("mapa.shared::cluster.u32 %0, %1, %2;" : "=r"(r) : "r"(addr), "r"(rank));
    return r;
}
__device__ __forceinline__ void st_cluster_u32(uint32_t addr, uint32_t v) {
    asm volatile("st.shared::cluster.u32 [%0], %1;" :: "r"(addr), "r"(v) : "memory");
}
__device__ __forceinline__ void cp_async16(uint32_t dst, const void* src) {
    asm volatile("cp.async.ca.shared.global [%0], [%1], 16;" :: "r"(dst), "l"(src) : "memory");
}
__device__ __forceinline__ void cp_commit() {
    asm volatile("cp.async.commit_group;" ::: "memory");
}
__device__ __forceinline__ void cp_wait1() {
    asm volatile("cp.async.wait_group 1;" ::: "memory");
}
__device__ __forceinline__ void mbar_init(uint32_t addr, uint32_t count) {
    asm volatile("mbarrier.init.shared.b64 [%0], %1;" :: "r"(addr), "r"(count) : "memory");
}
__device__ __forceinline__ void mbar_arrive_peer(uint32_t remote_addr) {
    asm volatile("mbarrier.arrive.release.cluster.shared::cluster.b64 _, [%0];"
                 :: "r"(remote_addr) : "memory");
}
__device__ __forceinline__ void mbar_wait_parity(uint32_t addr, uint32_t parity) {
    uint32_t done;
    asm volatile(
        "{\n\t.reg .pred p;\n\t"
        "mbarrier.try_wait.parity.acquire.cluster.shared::cta.b64 p, [%1], %2;\n\t"
        "selp.b32 %0, 1, 0, p;\n\t}"
        : "=r"(done) : "r"(addr), "r"(parity) : "memory");
    if (!done) {
        asm volatile(
            "{\n\t.reg .pred P1;\n\t"
            "WAIT_LOOP_%=:\n\t"
            "mbarrier.try_wait.parity.acquire.cluster.shared::cta.b64 P1, [%0], %1, 0x989680;\n\t"
            "@P1 bra.uni WAIT_DONE_%=;\n\t"
            "bra.uni WAIT_LOOP_%=;\n\t"
            "WAIT_DONE_%=:\n\t}"
            :: "r"(addr), "r"(parity) : "memory");
    }
}
#define CLUSTER_SYNC() do { \
    asm volatile("barrier.cluster.arrive.aligned;" ::: "memory"); \
    asm volatile("barrier.cluster.wait.aligned;" ::: "memory"); \
} while (0)

// ---------------------------------------------------------------------------
// K1/K3: gates GEMM on tf32 tensor cores (R7 code; epilogue -> fp16).
//   out (half): [dir][t][n=480][b=256].
// ---------------------------------------------------------------------------
#define ALD 36
#define MLD 136

template <int KDIM, bool GATHER>
__global__ __launch_bounds__(256, 2)
void gates_mma_kernel(const float* __restrict__ A, const int* __restrict__ xids,
                      const float* __restrict__ Wf, const float* __restrict__ Wb,
                      const float* __restrict__ bf, const float* __restrict__ bb,
                      __half* __restrict__ out) {
    const int m0 = blockIdx.x * 128;
    const int n0 = blockIdx.y * 96;
    const int dir = blockIdx.z;
    const float* W = dir ? Wb : Wf;
    const float* bias = dir ? bb : bf;
    __half* outp = out + (size_t)dir * Mrows * G3;

    __shared__ float As[128 * ALD];
    __shared__ float Bs[96 * ALD];
    __shared__ int rid[128];

    const int tid = threadIdx.x;
    if (GATHER) {
        if (tid < 128) {
            int m = m0 + tid;
            rid[tid] = xids[(m & 255) * Tt + (m >> 8)];
        }
        __syncthreads();
    }

    const int lane = tid & 31, wid = tid >> 5;
    const int grp = lane >> 2, tq = lane & 3;
    const int m_off = (wid >> 1) * 32;
    const int n_off = (wid & 1) * 48;

    float acc[2][6][4];
#pragma unroll
    for (int i = 0; i < 2; i++)
#pragma unroll
        for (int j = 0; j < 6; j++)
#pragma unroll
            for (int c = 0; c < 4; c++) acc[i][j][c] = 0.f;

    const int rA = tid >> 3;
    const int cA = tid & 7;
    const float* arow[4];
    if (GATHER) {
#pragma unroll
        for (int u = 0; u < 4; u++) arow[u] = A + (size_t)rid[rA + u * 32] * KDIM;
    }
    const float* Abase = GATHER ? nullptr
                        : A + ((size_t)(m0 >> 8) * KDIM) * 256 + (m0 & 255);

    const float* brow[3];
#pragma unroll
    for (int u = 0; u < 3; u++) brow[u] = W + (size_t)(n0 + rA + u * 32) * KDIM;

    const int KT = KDIM / 32;
    float4 aR[4], bR[3];

    if (GATHER) {
#pragma unroll
        for (int u = 0; u < 4; u++) aR[u] = *(const float4*)(arow[u] + cA * 4);
    } else {
#pragma unroll
        for (int u = 0; u < 4; u++) {
            int idx = u * 256 + tid;
            int k = idx >> 5, m4 = (idx & 31) * 4;
            aR[u] = *(const float4*)(Abase + (size_t)k * 256 + m4);
        }
    }
#pragma unroll
    for (int u = 0; u < 3; u++) bR[u] = *(const float4*)(brow[u] + cA * 4);

    for (int kt = 0; kt < KT; kt++) {
        __syncthreads();
        if (GATHER) {
#pragma unroll
            for (int u = 0; u < 4; u++) {
                float4 v = aR[u];
                float4 w4 = make_float4(__uint_as_float(f2tf32(v.x)), __uint_as_float(f2tf32(v.y)),
                                        __uint_as_float(f2tf32(v.z)), __uint_as_float(f2tf32(v.w)));
                *(float4*)&As[(rA + u * 32) * ALD + cA * 4] = w4;
            }
        } else {
#pragma unroll
            for (int u = 0; u < 4; u++) {
                int idx = u * 256 + tid;
                int k = idx >> 5, m4 = (idx & 31) * 4;
                float4 v = aR[u];
                float4 w4 = make_float4(__uint_as_float(f2tf32(v.x)), __uint_as_float(f2tf32(v.y)),
                                        __uint_as_float(f2tf32(v.z)), __uint_as_float(f2tf32(v.w)));
                *(float4*)&As[k * MLD + m4] = w4;
            }
        }
#pragma unroll
        for (int u = 0; u < 3; u++) {
            float4 v = bR[u];
            float4 w4 = make_float4(__uint_as_float(f2tf32(v.x)), __uint_as_float(f2tf32(v.y)),
                                    __uint_as_float(f2tf32(v.z)), __uint_as_float(f2tf32(v.w)));
            *(float4*)&Bs[(rA + u * 32) * ALD + cA * 4] = w4;
        }
        __syncthreads();

        if (kt + 1 < KT) {
            int ko = (kt + 1) * 32;
            if (GATHER) {
#pragma unroll
                for (int u = 0; u < 4; u++) aR[u] = *(const float4*)(arow[u] + ko + cA * 4);
            } else {
#pragma unroll
                for (int u = 0; u < 4; u++) {
                    int idx = u * 256 + tid;
                    int k = idx >> 5, m4 = (idx & 31) * 4;
                    aR[u] = *(const float4*)(Abase + (size_t)(ko + k) * 256 + m4);
                }
            }
#pragma unroll
            for (int u = 0; u < 3; u++) bR[u] = *(const float4*)(brow[u] + ko + cA * 4);
        }

#pragma unroll
        for (int kc = 0; kc < 4; kc++) {
            const int kk0 = kc * 8;
            uint32_t af[2][4];
            if (GATHER) {
#pragma unroll
                for (int i = 0; i < 2; i++) {
                    int rm = m_off + i * 16;
                    af[i][0] = __float_as_uint(As[(rm + grp) * ALD + kk0 + tq]);
                    af[i][1] = __float_as_uint(As[(rm + 8 + grp) * ALD + kk0 + tq]);
                    af[i][2] = __float_as_uint(As[(rm + grp) * ALD + kk0 + tq + 4]);
                    af[i][3] = __float_as_uint(As[(rm + 8 + grp) * ALD + kk0 + tq + 4]);
                }
            } else {
#pragma unroll
                for (int i = 0; i < 2; i++) {
                    int rm = m_off + i * 16;
                    af[i][0] = __float_as_uint(As[(kk0 + tq) * MLD + rm + grp]);
                    af[i][1] = __float_as_uint(As[(kk0 + tq) * MLD + rm + 8 + grp]);
                    af[i][2] = __float_as_uint(As[(kk0 + tq + 4) * MLD + rm + grp]);
                    af[i][3] = __float_as_uint(As[(kk0 + tq + 4) * MLD + rm + 8 + grp]);
                }
            }
            uint32_t bfr[6][2];
#pragma unroll
            for (int j = 0; j < 6; j++) {
                int nb = n_off + j * 8;
                bfr[j][0] = __float_as_uint(Bs[(nb + grp) * ALD + kk0 + tq]);
                bfr[j][1] = __float_as_uint(Bs[(nb + grp) * ALD + kk0 + tq + 4]);
            }
#pragma unroll
            for (int i = 0; i < 2; i++)
#pragma unroll
                for (int j = 0; j < 6; j++) mma_tf32(acc[i][j], af[i], bfr[j]);
        }
    }

    // epilogue -> half out[t][n][256]
    {
        const int t_t = m0 >> 8;
        const int bb = m0 & 255;
        __half* ob = outp + (size_t)t_t * G3 * 256 + bb;
#pragma unroll
        for (int j = 0; j < 6; j++) {
            int col = n0 + n_off + j * 8 + 2 * tq;
            float b0v = bias[col], b1v = bias[col + 1];
#pragma unroll
            for (int i = 0; i < 2; i++) {
                int ml = m_off + i * 16 + grp;
                ob[(size_t)col * 256 + ml]           = __float2half(acc[i][j][0] + b0v);
                ob[(size_t)(col + 1) * 256 + ml]     = __float2half(acc[i][j][1] + b1v);
                ob[(size_t)col * 256 + ml + 8]       = __float2half(acc[i][j][2] + b0v);
                ob[(size_t)(col + 1) * 256 + ml + 8] = __float2half(acc[i][j][3] + b1v);
            }
        }
    }
}

// ---------------------------------------------------------------------------
// K2/K4: GRU scan on tensor cores, 2-CTA cluster (R10 code; y0/hfin fp32).
//   k-split mma around the peer mbar wait; tanh.approx gates; gi (half)
//   staged one step ahead via 240 row-wise 16B cp.asyncs.
// ---------------------------------------------------------------------------
#define HST 168                  // h row stride (floats); 168 % 32 == 8
#define HBUFN (8 * HST)
#define GROWS 240                // gi rows staged per step (3 gates x 80 units)

__global__ __launch_bounds__(512) __cluster_dims__(2, 1, 1)
void scan_mma_kernel(const __half* __restrict__ gi,
                     const float* __restrict__ whhF, const float* __restrict__ whhB,
                     const float* __restrict__ bhf, const float* __restrict__ bhb,
                     float* __restrict__ yout, int layer) {
    __shared__ __align__(16) float hbuf[2][HBUFN];   // [buf][b][perm(k)] (tf32 bits)
    __shared__ float gh[240 * 8];                    // [lr][b]
    __shared__ __align__(16) __half gis[2][GROWS * 8];
    __shared__ __align__(8) unsigned long long mbar[2];

    const int dir = blockIdx.y;
    const int rank = blockIdx.x & 1;
    const int b0 = (blockIdx.x >> 1) * 8;
    const int tid = threadIdx.x;
    const int wid = tid >> 5, lane = tid & 31;
    const int grp = lane >> 2, tq = lane & 3;

    const uint32_t mbar0 = smem_u32(&mbar[0]);
    const uint32_t mbar1 = smem_u32(&mbar[1]);
    const uint32_t pbar0 = mapa_peer(mbar0, rank ^ 1);
    const uint32_t pbar1 = mapa_peer(mbar1, rank ^ 1);
    if (tid == 0) {
        mbar_init(mbar0, 1);
        mbar_init(mbar1, 1);
    }

    // ---- preload Whh A-fragments: [0..39] own-rank k half, [40..79] peer half ----
    uint32_t wreg[80];
    const bool is_mma = (wid < 15);
    const int ktL = rank * 10;
    const int ktR = (rank ^ 1) * 10;
    if (is_mma) {
        const int gate = wid / 5, mseg = wid % 5;
        const int gr0 = gate * Hh + rank * 80 + mseg * 16 + grp;
        const float* W = dir ? whhB : whhF;
#pragma unroll
        for (int j = 0; j < 10; j++) {
            int kt = ktL + j;
            wreg[j * 4 + 0] = f2tf32(W[(size_t)gr0 * Hh + kt * 8 + tq]);
            wreg[j * 4 + 1] = f2tf32(W[(size_t)(gr0 + 8) * Hh + kt * 8 + tq]);
            wreg[j * 4 + 2] = f2tf32(W[(size_t)gr0 * Hh + kt * 8 + tq + 4]);
            wreg[j * 4 + 3] = f2tf32(W[(size_t)(gr0 + 8) * Hh + kt * 8 + tq + 4]);
        }
#pragma unroll
        for (int j = 0; j < 10; j++) {
            int kt = ktR + j;
            wreg[40 + j * 4 + 0] = f2tf32(W[(size_t)gr0 * Hh + kt * 8 + tq]);
            wreg[40 + j * 4 + 1] = f2tf32(W[(size_t)(gr0 + 8) * Hh + kt * 8 + tq]);
            wreg[40 + j * 4 + 2] = f2tf32(W[(size_t)gr0 * Hh + kt * 8 + tq + 4]);
            wreg[40 + j * 4 + 3] = f2tf32(W[(size_t)(gr0 + 8) * Hh + kt * 8 + tq + 4]);
        }
    }

    // ---- combine-item setup ----
    const int uA = tid >> 3, bA = tid & 7;
    const int gA = rank * 80 + uA;
    const int pgA = (gA & ~7) | (((gA & 3) << 1) | ((gA >> 2) & 1));
    const float* bh = dir ? bhb : bhf;
    const float bhrA = bh[gA], bhzA = bh[Hh + gA], bhnA = bh[2 * Hh + gA];
    uint32_t prA[2];
    prA[0] = mapa_peer(smem_u32(&hbuf[0][bA * HST + pgA]), rank ^ 1);
    prA[1] = mapa_peer(smem_u32(&hbuf[1][bA * HST + pgA]), rank ^ 1);

    const bool hasB = (tid < 128);
    const int uB = 64 + (tid >> 3), gB = rank * 80 + uB;
    const int pgB = (gB & ~7) | (((gB & 3) << 1) | ((gB >> 2) & 1));
    float bhrB = 0.f, bhzB = 0.f, bhnB = 0.f;
    uint32_t prB[2] = {0u, 0u};
    if (hasB) {
        bhrB = bh[gB]; bhzB = bh[Hh + gB]; bhnB = bh[2 * Hh + gB];
        prB[0] = mapa_peer(smem_u32(&hbuf[0][bA * HST + pgB]), rank ^ 1);
        prB[1] = mapa_peer(smem_u32(&hbuf[1][bA * HST + pgB]), rank ^ 1);
    }

    // ---- gi staging: thread r<240 owns one (gate,unit) row of 8 halves ----
    const __half* gib = gi + (size_t)dir * Mrows * G3;
    const bool is_ld = (tid < GROWS);
    const int rgate = tid / 80;
    const int runit = tid - rgate * 80;
    const int rn = rgate * 160 + rank * 80 + runit;
    const __half* srcRow = gib + (size_t)rn * 256 + b0;
    const uint32_t gis_base = smem_u32(&gis[0][0]);
    const uint32_t dstRow = gis_base + (uint32_t)tid * 16;

    for (int i = tid; i < 2 * HBUFN; i += 512) (&hbuf[0][0])[i] = 0.f;

    // prologue: stage gi for s=0 into slot 0
    {
        const int t0 = dir ? (Tt - 1) : 0;
        if (is_ld) cp_async16(dstRow, srcRow + (size_t)t0 * G3 * 256);
        cp_commit();
    }

    __syncthreads();
    CLUSTER_SYNC();

    float hA = 0.f, hB = 0.f;
    int cur = 0;

    for (int s = 0; s < Tt; s++) {
        if (s + 1 < Tt) {
            const int tn = dir ? (Tt - 2 - s) : (s + 1);
            if (is_ld) cp_async16(dstRow + (cur ^ 1) * (GROWS * 16),
                                  srcRow + (size_t)tn * G3 * 256);
        }
        cp_commit();

        if (is_mma) {
            float accA[4] = {0.f, 0.f, 0.f, 0.f};
            float accB4[4] = {0.f, 0.f, 0.f, 0.f};
            const float* hc = hbuf[cur];
            const int hbase = grp * HST;

            // phase L: own-half k (no peer dependency)
#pragma unroll
            for (int j = 0; j < 10; j += 2) {
                float2 v0 = *(const float2*)&hc[hbase + (ktL + j) * 8 + tq * 2];
                mma_tf32(accA, &wreg[j * 4], (const uint32_t*)&v0);
                float2 v1 = *(const float2*)&hc[hbase + (ktL + j + 1) * 8 + tq * 2];
                mma_tf32(accB4, &wreg[(j + 1) * 4], (const uint32_t*)&v1);
            }

            if (s > 0) {
                mbar_wait_parity((s & 1) ? mbar1 : mbar0, ((s - 1) >> 1) & 1);
            }

            // phase R: peer-half k
#pragma unroll
            for (int j = 0; j < 10; j += 2) {
                float2 v0 = *(const float2*)&hc[hbase + (ktR + j) * 8 + tq * 2];
                mma_tf32(accA, &wreg[40 + j * 4], (const uint32_t*)&v0);
                float2 v1 = *(const float2*)&hc[hbase + (ktR + j + 1) * 8 + tq * 2];
                mma_tf32(accB4, &wreg[40 + (j + 1) * 4], (const uint32_t*)&v1);
            }

            const int lr = wid * 16;
            *(float2*)&gh[(lr + grp) * 8 + 2 * tq] =
                make_float2(accA[0] + accB4[0], accA[1] + accB4[1]);
            *(float2*)&gh[(lr + 8 + grp) * 8 + 2 * tq] =
                make_float2(accA[2] + accB4[2], accA[3] + accB4[3]);
        }
        cp_wait1();
        __syncthreads();

        const int t = dir ? (Tt - 1 - s) : s;
        const int nxt = cur ^ 1;
        const __half* gs = &gis[cur][0];
        {
            float gir = __half2float(gs[(0 * 80 + uA) * 8 + bA]);
            float giz = __half2float(gs[(1 * 80 + uA) * 8 + bA]);
            float gin = __half2float(gs[(2 * 80 + uA) * 8 + bA]);
            float r = fmaf(tanh_ap(0.5f * (gir + gh[uA * 8 + bA] + bhrA)), 0.5f, 0.5f);
            float z = fmaf(tanh_ap(0.5f * (giz + gh[(80 + uA) * 8 + bA] + bhzA)), 0.5f, 0.5f);
            float n = tanh_ap(gin + r * (gh[(160 + uA) * 8 + bA] + bhnA));
            hA = fmaf(z, hA - n, n);
            uint32_t htf = f2tf32(hA);
            *(uint32_t*)&hbuf[nxt][bA * HST + pgA] = htf;
            st_cluster_u32(prA[nxt], htf);
            if (layer == 0)
                yout[((size_t)t * 320 + dir * Hh + gA) * 256 + b0 + bA] = hA;
        }
        if (hasB) {
            float gir = __half2float(gs[(0 * 80 + uB) * 8 + bA]);
            float giz = __half2float(gs[(1 * 80 + uB) * 8 + bA]);
            float gin = __half2float(gs[(2 * 80 + uB) * 8 + bA]);
            float r = fmaf(tanh_ap(0.5f * (gir + gh[uB * 8 + bA] + bhrB)), 0.5f, 0.5f);
            float z = fmaf(tanh_ap(0.5f * (giz + gh[(80 + uB) * 8 + bA] + bhzB)), 0.5f, 0.5f);
            float n = tanh_ap(gin + r * (gh[(160 + uB) * 8 + bA] + bhnB));
            hB = fmaf(z, hB - n, n);
            uint32_t htf = f2tf32(hB);
            *(uint32_t*)&hbuf[nxt][bA * HST + pgB] = htf;
            st_cluster_u32(prB[nxt], htf);
            if (layer == 0)
                yout[((size_t)t * 320 + dir * Hh + gB) * 256 + b0 + bA] = hB;
        }
        __syncthreads();   // all peer stores issued before the release below
        if (tid == 0) {
            mbar_arrive_peer((nxt & 1) ? pbar1 : pbar0);
        }
        cur = nxt;
    }

    if (layer == 1) {
        yout[((size_t)(dir * Bb) + b0 + bA) * Hh + gA] = hA;
        if (hasB) yout[((size_t)(dir * Bb) + b0 + bA) * Hh + gB] = hB;
    }
    CLUSTER_SYNC();   // no CTA exits while peer stores into its smem may be in flight
}

// ---------------------------------------------------------------------------
// K5: head
// ---------------------------------------------------------------------------
__global__ __launch_bounds__(128)
void head_kernel(const float* __restrict__ hfin,
                 const float* __restrict__ fc1w, const float* __restrict__ fc1b,
                 const float* __restrict__ fc2w, const float* __restrict__ fc2b,
                 float* __restrict__ out) {
    const int b = blockIdx.x;
    const int j = threadIdx.x;
    __shared__ float hv[320];
    __shared__ float red[4];

    for (int k = j; k < Hh; k += 128) {
        hv[k]      = hfin[(size_t)b * Hh + k];
        hv[Hh + k] = hfin[(size_t)Bb * Hh + (size_t)b * Hh + k];
    }
    __syncthreads();

    float acc = fc1b[j];
    const float* wr = fc1w + (size_t)j * 320;
#pragma unroll 8
    for (int k = 0; k < 320; k++) acc += wr[k] * hv[k];
    float v = fmaxf(acc, 0.f) * fc2w[j];

#pragma unroll
    for (int o = 16; o > 0; o >>= 1) v += __shfl_down_sync(0xffffffffu, v, o);
    if ((j & 31) == 0) red[j >> 5] = v;
    __syncthreads();
    if (j == 0) out[b] = red[0] + red[1] + red[2] + red[3] + fc2b[0];
}

// ---------------------------------------------------------------------------
// kernel_launch — sequential pipeline (graph-capturable, profiler-safe)
// ---------------------------------------------------------------------------
extern "C" void kernel_launch(void* const* d_in, const int* in_sizes, int n_in,
                              void* d_out, int out_size) {
    const int*   x        = (const int*)  d_in[0];
    const float* emb      = (const float*)d_in[1];
    const float* Wih_l0f  = (const float*)d_in[2];
    const float* Whh_l0f  = (const float*)d_in[3];
    const float* bih_l0f  = (const float*)d_in[4];
    const float* bhh_l0f  = (const float*)d_in[5];
    const float* Wih_l0b  = (const float*)d_in[6];
    const float* Whh_l0b  = (const float*)d_in[7];
    const float* bih_l0b  = (const float*)d_in[8];
    const float* bhh_l0b  = (const float*)d_in[9];
    const float* Wih_l1f  = (const float*)d_in[10];
    const float* Whh_l1f  = (const float*)d_in[11];
    const float* bih_l1f  = (const float*)d_in[12];
    const float* bhh_l1f  = (const float*)d_in[13];
    const float* Wih_l1b  = (const float*)d_in[14];
    const float* Whh_l1b  = (const float*)d_in[15];
    const float* bih_l1b  = (const float*)d_in[16];
    const float* bhh_l1b  = (const float*)d_in[17];
    const float* fc1_w    = (const float*)d_in[18];
    const float* fc1_b    = (const float*)d_in[19];
    const float* fc2_w    = (const float*)d_in[20];
    const float* fc2_b    = (const float*)d_in[21];
    float* out = (float*)d_out;

    __half *gi0, *gi1;
    float *y0, *hfin;
    cudaGetSymbolAddress((void**)&gi0,  g_gi0);
    cudaGetSymbolAddress((void**)&gi1,  g_gi1);
    cudaGetSymbolAddress((void**)&y0,   g_y0);
    cudaGetSymbolAddress((void**)&hfin, g_hfin);

    {
        dim3 grid(Mrows / 128, G3 / 96, 2);
        gates_mma_kernel<128, true><<<grid, 256>>>(emb, x, Wih_l0f, Wih_l0b,
                                                   bih_l0f, bih_l0b, gi0);
    }

    scan_mma_kernel<<<dim3(64, 2), 512>>>(gi0, Whh_l0f, Whh_l0b,
                                          bhh_l0f, bhh_l0b, y0, 0);

    {
        dim3 grid(Mrows / 128, G3 / 96, 2);
        gates_mma_kernel<320, false><<<grid, 256>>>(y0, nullptr, Wih_l1f, Wih_l1b,
                                                    bih_l1f, bih_l1b, gi1);
    }

    scan_mma_kernel<<<dim3(64, 2), 512>>>(gi1, Whh_l1f, Whh_l1b,
                                          bhh_l1f, bhh_l1b, hfin, 1);

    head_kernel<<<Bb, 128>>>(hfin, fc1_w, fc1_b, fc2_w, fc2_b, out);
}

// round 13
// speedup vs baseline: 1.1796x; 1.0937x over previous
#include <cuda_runtime.h>
#include <cuda_fp16.h>
#include <math.h>
#include <stdint.h>

// ---------------------------------------------------------------------------
// TextGRUClassifier: 2-layer bidir GRU (B=256,T=512,E=128,H=160) + FC head
// R13 = R12 scans (cluster, fp16 gi) + GEMMs moved to m16n8k16.f16 mma
// (same 10-bit mantissa as tf32; halves mma count, fragment loads become
// LDS.64 via k-permuted 16-groups). y0 now m-major [t][b][320] fp32 so
// GEMM1's A is row-major like GEMM0's (unified fragment path).
// ---------------------------------------------------------------------------

#define Tt 512
#define Bb 256
#define Hh 160
#define G3 480
#define Mrows (Tt*Bb)     // 131072

// ---- scratch ----
static __device__ __half g_gi0[(size_t)2 * Mrows * G3];  // [dir][t][n=480][b=256]
static __device__ __half g_gi1[(size_t)2 * Mrows * G3];
static __device__ float  g_y0[(size_t)Mrows * 320];      // [t][b][320] fp32 (m-major)
static __device__ float  g_hfin[2 * Bb * Hh];            // [dir][b][g]

// ---- helpers ----
__device__ __forceinline__ float tanh_ap(float x) {
    float r;
    asm("tanh.approx.f32 %0, %1;" : "=f"(r) : "f"(x));
    return r;
}
__device__ __forceinline__ uint32_t f2tf32(float x) {
    uint32_t r;
    asm("cvt.rna.tf32.f32 %0, %1;" : "=r"(r) : "f"(x));
    return r;
}
__device__ __forceinline__ void mma_tf32(float* d, const uint32_t* a, const uint32_t* b) {
    asm volatile(
        "mma.sync.aligned.m16n8k8.row.col.f32.tf32.tf32.f32 "
        "{%0,%1,%2,%3}, {%4,%5,%6,%7}, {%8,%9}, {%0,%1,%2,%3};"
        : "+f"(d[0]), "+f"(d[1]), "+f"(d[2]), "+f"(d[3])
        : "r"(a[0]), "r"(a[1]), "r"(a[2]), "r"(a[3]), "r"(b[0]), "r"(b[1]));
}
__device__ __forceinline__ void mma_f16(float* d, const uint32_t* a, uint32_t b0, uint32_t b1) {
    asm volatile(
        "mma.sync.aligned.m16n8k16.row.col.f32.f16.f16.f32 "
        "{%0,%1,%2,%3}, {%4,%5,%6,%7}, {%8,%9}, {%0,%1,%2,%3};"
        : "+f"(d[0]), "+f"(d[1]), "+f"(d[2]), "+f"(d[3])
        : "r"(a[0]), "r"(a[1]), "r"(a[2]), "r"(a[3]), "r"(b0), "r"(b1));
}
__device__ __forceinline__ uint32_t smem_u32(const void* p) {
    uint32_t a;
    asm("{ .reg .u64 t; cvta.to.shared.u64 t, %1; cvt.u32.u64 %0, t; }" : "=r"(a) : "l"(p));
    return a;
}
__device__ __forceinline__ uint32_t mapa_peer(uint32_t addr, uint32_t rank) {
    uint32_t r;
    asm("mapa.shared::cluster.u32 %0, %1, %2;" : "=r"(r) : "r"(addr), "r"(rank));
    return r;
}
__device__ __forceinline__ void st_cluster_u32(uint32_t addr, uint32_t v) {
    asm volatile("st.shared::cluster.u32 [%0], %1;" :: "r"(addr), "r"(v) : "memory");
}
__device__ __forceinline__ void cp_async16(uint32_t dst, const void* src) {
    asm volatile("cp.async.ca.shared.global [%0], [%1], 16;" :: "r"(dst), "l"(src) : "memory");
}
__device__ __forceinline__ void cp_commit() {
    asm volatile("cp.async.commit_group;" ::: "memory");
}
__device__ __forceinline__ void cp_wait1() {
    asm volatile("cp.async.wait_group 1;" ::: "memory");
}
__device__ __forceinline__ void mbar_init(uint32_t addr, uint32_t count) {
    asm volatile("mbarrier.init.shared.b64 [%0], %1;" :: "r"(addr), "r"(count) : "memory");
}
__device__ __forceinline__ void mbar_arrive_peer(uint32_t remote_addr) {
    asm volatile("mbarrier.arrive.release.cluster.shared::cluster.b64 _, [%0];"
                 :: "r"(remote_addr) : "memory");
}
__device__ __forceinline__ void mbar_wait_parity(uint32_t addr, uint32_t parity) {
    uint32_t done;
    asm volatile(
        "{\n\t.reg .pred p;\n\t"
        "mbarrier.try_wait.parity.acquire.cluster.shared::cta.b64 p, [%1], %2;\n\t"
        "selp.b32 %0, 1, 0, p;\n\t}"
        : "=r"(done) : "r"(addr), "r"(parity) : "memory");
    if (!done) {
        asm volatile(
            "{\n\t.reg .pred P1;\n\t"
            "WAIT_LOOP_%=:\n\t"
            "mbarrier.try_wait.parity.acquire.cluster.shared::cta.b64 P1, [%0], %1, 0x989680;\n\t"
            "@P1 bra.uni WAIT_DONE_%=;\n\t"
            "bra.uni WAIT_LOOP_%=;\n\t"
            "WAIT_DONE_%=:\n\t}"
            :: "r"(addr), "r"(parity) : "memory");
    }
}
#define CLUSTER_SYNC() do { \
    asm volatile("barrier.cluster.arrive.aligned;" ::: "memory"); \
    asm volatile("barrier.cluster.wait.aligned;" ::: "memory"); \
} while (0)

// ---------------------------------------------------------------------------
// K1/K3: gates GEMM on f16 tensor cores (m16n8k16, fp32 accum).
//   out (half): [dir][t][n=480][b=256].
//   A: row-major fp32 rows (GEMM0: gathered emb rows; GEMM1: y0[t][b][320]).
//   Smem tiles (half): row stride 48 halves; k 16-groups permuted
//   [k0k1 k8k9 | k2k3 k10k11 | k4k5 k12k13 | k6k7 k14k15] so a fragment's
//   (2tq,2tq+1,2tq+8,2tq+9) is one 8-byte LDS.
// ---------------------------------------------------------------------------
#define HRS 48    // halves per smem tile row (conflict-free fragment loads)

template <int KDIM, bool GATHER>
__global__ __launch_bounds__(256, 2)
void gates_mma_kernel(const float* __restrict__ A, const int* __restrict__ xids,
                      const float* __restrict__ Wf, const float* __restrict__ Wb,
                      const float* __restrict__ bf, const float* __restrict__ bb,
                      __half* __restrict__ out) {
    const int m0 = blockIdx.x * 128;
    const int n0 = blockIdx.y * 96;
    const int dir = blockIdx.z;
    const float* W = dir ? Wb : Wf;
    const float* bias = dir ? bb : bf;
    __half* outp = out + (size_t)dir * Mrows * G3;

    __shared__ __align__(16) __half Ash[128 * HRS];   // 12288 B
    __shared__ __align__(16) __half Bsh[96 * HRS];    // 9216 B
    __shared__ int rid[128];

    const int tid = threadIdx.x;
    if (GATHER) {
        if (tid < 128) {
            int m = m0 + tid;
            rid[tid] = xids[(m & 255) * Tt + (m >> 8)];
        }
        __syncthreads();
    }

    const int lane = tid & 31, wid = tid >> 5;
    const int grp = lane >> 2, tq = lane & 3;
    const int m_off = (wid >> 1) * 32;
    const int n_off = (wid & 1) * 48;

    float acc[2][6][4];
#pragma unroll
    for (int i = 0; i < 2; i++)
#pragma unroll
        for (int j = 0; j < 6; j++)
#pragma unroll
            for (int c = 0; c < 4; c++) acc[i][j][c] = 0.f;

    const int rA = tid >> 3;       // 0..31
    const int cA = tid & 7;        // 0..7 -> k = cA*4..cA*4+3
    const int gS = cA >> 2;        // 16-group within BK=32
    const int cS = cA & 3;         // float4 index within group
    // permuted half-slots for pairs (2c, 2c+1) within the 16-group
    const int s1 = (cS < 2) ? cS * 8 : (cS - 2) * 8 + 2;
    const int s2 = s1 + 4;

    const float* arow[4];
#pragma unroll
    for (int u = 0; u < 4; u++) {
        int r = rA + u * 32;
        arow[u] = GATHER ? A + (size_t)rid[r] * KDIM
                         : A + (size_t)(m0 + r) * KDIM;
    }
    const float* brow[3];
#pragma unroll
    for (int u = 0; u < 3; u++) brow[u] = W + (size_t)(n0 + rA + u * 32) * KDIM;

    const int KT = KDIM / 32;
    float4 aR[4], bR[3];

#pragma unroll
    for (int u = 0; u < 4; u++) aR[u] = *(const float4*)(arow[u] + cA * 4);
#pragma unroll
    for (int u = 0; u < 3; u++) bR[u] = *(const float4*)(brow[u] + cA * 4);

    for (int kt = 0; kt < KT; kt++) {
        __syncthreads();
#pragma unroll
        for (int u = 0; u < 4; u++) {
            float4 v = aR[u];
            __half* row = &Ash[(rA + u * 32) * HRS + gS * 16];
            *(__half2*)(row + s1) = __floats2half2_rn(v.x, v.y);
            *(__half2*)(row + s2) = __floats2half2_rn(v.z, v.w);
        }
#pragma unroll
        for (int u = 0; u < 3; u++) {
            float4 v = bR[u];
            __half* row = &Bsh[(rA + u * 32) * HRS + gS * 16];
            *(__half2*)(row + s1) = __floats2half2_rn(v.x, v.y);
            *(__half2*)(row + s2) = __floats2half2_rn(v.z, v.w);
        }
        __syncthreads();

        if (kt + 1 < KT) {
            int ko = (kt + 1) * 32 + cA * 4;
#pragma unroll
            for (int u = 0; u < 4; u++) aR[u] = *(const float4*)(arow[u] + ko);
#pragma unroll
            for (int u = 0; u < 3; u++) bR[u] = *(const float4*)(brow[u] + ko);
        }

#pragma unroll
        for (int g = 0; g < 2; g++) {
            const int goff = g * 16 + tq * 4;
            uint32_t af[2][4];
#pragma unroll
            for (int i = 0; i < 2; i++) {
                int rm = m_off + i * 16;
                uint2 v0 = *(const uint2*)&Ash[(rm + grp) * HRS + goff];
                uint2 v1 = *(const uint2*)&Ash[(rm + 8 + grp) * HRS + goff];
                af[i][0] = v0.x; af[i][1] = v1.x; af[i][2] = v0.y; af[i][3] = v1.y;
            }
#pragma unroll
            for (int j = 0; j < 6; j++) {
                uint2 bv = *(const uint2*)&Bsh[(n_off + j * 8 + grp) * HRS + goff];
                mma_f16(acc[0][j], af[0], bv.x, bv.y);
                mma_f16(acc[1][j], af[1], bv.x, bv.y);
            }
        }
    }

    // epilogue -> half out[t][n][256]
    {
        const int t_t = m0 >> 8;
        const int bb = m0 & 255;
        __half* ob = outp + (size_t)t_t * G3 * 256 + bb;
#pragma unroll
        for (int j = 0; j < 6; j++) {
            int col = n0 + n_off + j * 8 + 2 * tq;
            float b0v = bias[col], b1v = bias[col + 1];
#pragma unroll
            for (int i = 0; i < 2; i++) {
                int ml = m_off + i * 16 + grp;
                ob[(size_t)col * 256 + ml]           = __float2half(acc[i][j][0] + b0v);
                ob[(size_t)(col + 1) * 256 + ml]     = __float2half(acc[i][j][1] + b1v);
                ob[(size_t)col * 256 + ml + 8]       = __float2half(acc[i][j][2] + b0v);
                ob[(size_t)(col + 1) * 256 + ml + 8] = __float2half(acc[i][j][3] + b1v);
            }
        }
    }
}

// ---------------------------------------------------------------------------
// K2/K4: GRU scan on tensor cores, 2-CTA cluster (R12 code; y0 now m-major).
// ---------------------------------------------------------------------------
#define HST 168                  // h row stride (floats); 168 % 32 == 8
#define HBUFN (8 * HST)
#define GROWS 240                // gi rows staged per step (3 gates x 80 units)

__global__ __launch_bounds__(512) __cluster_dims__(2, 1, 1)
void scan_mma_kernel(const __half* __restrict__ gi,
                     const float* __restrict__ whhF, const float* __restrict__ whhB,
                     const float* __restrict__ bhf, const float* __restrict__ bhb,
                     float* __restrict__ yout, int layer) {
    __shared__ __align__(16) float hbuf[2][HBUFN];   // [buf][b][perm(k)] (tf32 bits)
    __shared__ float gh[240 * 8];                    // [lr][b]
    __shared__ __align__(16) __half gis[2][GROWS * 8];
    __shared__ __align__(8) unsigned long long mbar[2];

    const int dir = blockIdx.y;
    const int rank = blockIdx.x & 1;
    const int b0 = (blockIdx.x >> 1) * 8;
    const int tid = threadIdx.x;
    const int wid = tid >> 5, lane = tid & 31;
    const int grp = lane >> 2, tq = lane & 3;

    const uint32_t mbar0 = smem_u32(&mbar[0]);
    const uint32_t mbar1 = smem_u32(&mbar[1]);
    const uint32_t pbar0 = mapa_peer(mbar0, rank ^ 1);
    const uint32_t pbar1 = mapa_peer(mbar1, rank ^ 1);
    if (tid == 0) {
        mbar_init(mbar0, 1);
        mbar_init(mbar1, 1);
    }

    // ---- preload Whh A-fragments: [0..39] own-rank k half, [40..79] peer half ----
    uint32_t wreg[80];
    const bool is_mma = (wid < 15);
    const int ktL = rank * 10;
    const int ktR = (rank ^ 1) * 10;
    if (is_mma) {
        const int gate = wid / 5, mseg = wid % 5;
        const int gr0 = gate * Hh + rank * 80 + mseg * 16 + grp;
        const float* W = dir ? whhB : whhF;
#pragma unroll
        for (int j = 0; j < 10; j++) {
            int kt = ktL + j;
            wreg[j * 4 + 0] = f2tf32(W[(size_t)gr0 * Hh + kt * 8 + tq]);
            wreg[j * 4 + 1] = f2tf32(W[(size_t)(gr0 + 8) * Hh + kt * 8 + tq]);
            wreg[j * 4 + 2] = f2tf32(W[(size_t)gr0 * Hh + kt * 8 + tq + 4]);
            wreg[j * 4 + 3] = f2tf32(W[(size_t)(gr0 + 8) * Hh + kt * 8 + tq + 4]);
        }
#pragma unroll
        for (int j = 0; j < 10; j++) {
            int kt = ktR + j;
            wreg[40 + j * 4 + 0] = f2tf32(W[(size_t)gr0 * Hh + kt * 8 + tq]);
            wreg[40 + j * 4 + 1] = f2tf32(W[(size_t)(gr0 + 8) * Hh + kt * 8 + tq]);
            wreg[40 + j * 4 + 2] = f2tf32(W[(size_t)gr0 * Hh + kt * 8 + tq + 4]);
            wreg[40 + j * 4 + 3] = f2tf32(W[(size_t)(gr0 + 8) * Hh + kt * 8 + tq + 4]);
        }
    }

    // ---- combine-item setup ----
    const int uA = tid >> 3, bA = tid & 7;
    const int gA = rank * 80 + uA;
    const int pgA = (gA & ~7) | (((gA & 3) << 1) | ((gA >> 2) & 1));
    const float* bh = dir ? bhb : bhf;
    const float bhrA = bh[gA], bhzA = bh[Hh + gA], bhnA = bh[2 * Hh + gA];
    uint32_t prA[2];
    prA[0] = mapa_peer(smem_u32(&hbuf[0][bA * HST + pgA]), rank ^ 1);
    prA[1] = mapa_peer(smem_u32(&hbuf[1][bA * HST + pgA]), rank ^ 1);

    const bool hasB = (tid < 128);
    const int uB = 64 + (tid >> 3), gB = rank * 80 + uB;
    const int pgB = (gB & ~7) | (((gB & 3) << 1) | ((gB >> 2) & 1));
    float bhrB = 0.f, bhzB = 0.f, bhnB = 0.f;
    uint32_t prB[2] = {0u, 0u};
    if (hasB) {
        bhrB = bh[gB]; bhzB = bh[Hh + gB]; bhnB = bh[2 * Hh + gB];
        prB[0] = mapa_peer(smem_u32(&hbuf[0][bA * HST + pgB]), rank ^ 1);
        prB[1] = mapa_peer(smem_u32(&hbuf[1][bA * HST + pgB]), rank ^ 1);
    }

    // ---- gi staging: thread r<240 owns one (gate,unit) row of 8 halves ----
    const __half* gib = gi + (size_t)dir * Mrows * G3;
    const bool is_ld = (tid < GROWS);
    const int rgate = tid / 80;
    const int runit = tid - rgate * 80;
    const int rn = rgate * 160 + rank * 80 + runit;
    const __half* srcRow = gib + (size_t)rn * 256 + b0;
    const uint32_t gis_base = smem_u32(&gis[0][0]);
    const uint32_t dstRow = gis_base + (uint32_t)tid * 16;

    for (int i = tid; i < 2 * HBUFN; i += 512) (&hbuf[0][0])[i] = 0.f;

    // prologue: stage gi for s=0 into slot 0
    {
        const int t0 = dir ? (Tt - 1) : 0;
        if (is_ld) cp_async16(dstRow, srcRow + (size_t)t0 * G3 * 256);
        cp_commit();
    }

    __syncthreads();
    CLUSTER_SYNC();

    float hA = 0.f, hB = 0.f;
    int cur = 0;

    for (int s = 0; s < Tt; s++) {
        if (s + 1 < Tt) {
            const int tn = dir ? (Tt - 2 - s) : (s + 1);
            if (is_ld) cp_async16(dstRow + (cur ^ 1) * (GROWS * 16),
                                  srcRow + (size_t)tn * G3 * 256);
        }
        cp_commit();

        if (is_mma) {
            float accA[4] = {0.f, 0.f, 0.f, 0.f};
            float accB4[4] = {0.f, 0.f, 0.f, 0.f};
            const float* hc = hbuf[cur];
            const int hbase = grp * HST;

            // phase L: own-half k (no peer dependency)
#pragma unroll
            for (int j = 0; j < 10; j += 2) {
                float2 v0 = *(const float2*)&hc[hbase + (ktL + j) * 8 + tq * 2];
                mma_tf32(accA, &wreg[j * 4], (const uint32_t*)&v0);
                float2 v1 = *(const float2*)&hc[hbase + (ktL + j + 1) * 8 + tq * 2];
                mma_tf32(accB4, &wreg[(j + 1) * 4], (const uint32_t*)&v1);
            }

            if (s > 0) {
                mbar_wait_parity((s & 1) ? mbar1 : mbar0, ((s - 1) >> 1) & 1);
            }

            // phase R: peer-half k
#pragma unroll
            for (int j = 0; j < 10; j += 2) {
                float2 v0 = *(const float2*)&hc[hbase + (ktR + j) * 8 + tq * 2];
                mma_tf32(accA, &wreg[40 + j * 4], (const uint32_t*)&v0);
                float2 v1 = *(const float2*)&hc[hbase + (ktR + j + 1) * 8 + tq * 2];
                mma_tf32(accB4, &wreg[40 + (j + 1) * 4], (const uint32_t*)&v1);
            }

            const int lr = wid * 16;
            *(float2*)&gh[(lr + grp) * 8 + 2 * tq] =
                make_float2(accA[0] + accB4[0], accA[1] + accB4[1]);
            *(float2*)&gh[(lr + 8 + grp) * 8 + 2 * tq] =
                make_float2(accA[2] + accB4[2], accA[3] + accB4[3]);
        }
        cp_wait1();
        __syncthreads();

        const int t = dir ? (Tt - 1 - s) : s;
        const int nxt = cur ^ 1;
        const __half* gs = &gis[cur][0];
        {
            float gir = __half2float(gs[(0 * 80 + uA) * 8 + bA]);
            float giz = __half2float(gs[(1 * 80 + uA) * 8 + bA]);
            float gin = __half2float(gs[(2 * 80 + uA) * 8 + bA]);
            float r = fmaf(tanh_ap(0.5f * (gir + gh[uA * 8 + bA] + bhrA)), 0.5f, 0.5f);
            float z = fmaf(tanh_ap(0.5f * (giz + gh[(80 + uA) * 8 + bA] + bhzA)), 0.5f, 0.5f);
            float n = tanh_ap(gin + r * (gh[(160 + uA) * 8 + bA] + bhnA));
            hA = fmaf(z, hA - n, n);
            uint32_t htf = f2tf32(hA);
            *(uint32_t*)&hbuf[nxt][bA * HST + pgA] = htf;
            st_cluster_u32(prA[nxt], htf);
            if (layer == 0)
                yout[((size_t)t * 256 + b0 + bA) * 320 + dir * Hh + gA] = hA;
        }
        if (hasB) {
            float gir = __half2float(gs[(0 * 80 + uB) * 8 + bA]);
            float giz = __half2float(gs[(1 * 80 + uB) * 8 + bA]);
            float gin = __half2float(gs[(2 * 80 + uB) * 8 + bA]);
            float r = fmaf(tanh_ap(0.5f * (gir + gh[uB * 8 + bA] + bhrB)), 0.5f, 0.5f);
            float z = fmaf(tanh_ap(0.5f * (giz + gh[(80 + uB) * 8 + bA] + bhzB)), 0.5f, 0.5f);
            float n = tanh_ap(gin + r * (gh[(160 + uB) * 8 + bA] + bhnB));
            hB = fmaf(z, hB - n, n);
            uint32_t htf = f2tf32(hB);
            *(uint32_t*)&hbuf[nxt][bA * HST + pgB] = htf;
            st_cluster_u32(prB[nxt], htf);
            if (layer == 0)
                yout[((size_t)t * 256 + b0 + bA) * 320 + dir * Hh + gB] = hB;
        }
        __syncthreads();   // all peer stores issued before the release below
        if (tid == 0) {
            mbar_arrive_peer((nxt & 1) ? pbar1 : pbar0);
        }
        cur = nxt;
    }

    if (layer == 1) {
        yout[((size_t)(dir * Bb) + b0 + bA) * Hh + gA] = hA;
        if (hasB) yout[((size_t)(dir * Bb) + b0 + bA) * Hh + gB] = hB;
    }
    CLUSTER_SYNC();   // no CTA exits while peer stores into its smem may be in flight
}

// ---------------------------------------------------------------------------
// K5: head
// ---------------------------------------------------------------------------
__global__ __launch_bounds__(128)
void head_kernel(const float* __restrict__ hfin,
                 const float* __restrict__ fc1w, const float* __restrict__ fc1b,
                 const float* __restrict__ fc2w, const float* __restrict__ fc2b,
                 float* __restrict__ out) {
    const int b = blockIdx.x;
    const int j = threadIdx.x;
    __shared__ float hv[320];
    __shared__ float red[4];

    for (int k = j; k < Hh; k += 128) {
        hv[k]      = hfin[(size_t)b * Hh + k];
        hv[Hh + k] = hfin[(size_t)Bb * Hh + (size_t)b * Hh + k];
    }
    __syncthreads();

    float acc = fc1b[j];
    const float* wr = fc1w + (size_t)j * 320;
#pragma unroll 8
    for (int k = 0; k < 320; k++) acc += wr[k] * hv[k];
    float v = fmaxf(acc, 0.f) * fc2w[j];

#pragma unroll
    for (int o = 16; o > 0; o >>= 1) v += __shfl_down_sync(0xffffffffu, v, o);
    if ((j & 31) == 0) red[j >> 5] = v;
    __syncthreads();
    if (j == 0) out[b] = red[0] + red[1] + red[2] + red[3] + fc2b[0];
}

// ---------------------------------------------------------------------------
// kernel_launch — sequential pipeline (graph-capturable, profiler-safe)
// ---------------------------------------------------------------------------
extern "C" void kernel_launch(void* const* d_in, const int* in_sizes, int n_in,
                              void* d_out, int out_size) {
    const int*   x        = (const int*)  d_in[0];
    const float* emb      = (const float*)d_in[1];
    const float* Wih_l0f  = (const float*)d_in[2];
    const float* Whh_l0f  = (const float*)d_in[3];
    const float* bih_l0f  = (const float*)d_in[4];
    const float* bhh_l0f  = (const float*)d_in[5];
    const float* Wih_l0b  = (const float*)d_in[6];
    const float* Whh_l0b  = (const float*)d_in[7];
    const float* bih_l0b  = (const float*)d_in[8];
    const float* bhh_l0b  = (const float*)d_in[9];
    const float* Wih_l1f  = (const float*)d_in[10];
    const float* Whh_l1f  = (const float*)d_in[11];
    const float* bih_l1f  = (const float*)d_in[12];
    const float* bhh_l1f  = (const float*)d_in[13];
    const float* Wih_l1b  = (const float*)d_in[14];
    const float* Whh_l1b  = (const float*)d_in[15];
    const float* bih_l1b  = (const float*)d_in[16];
    const float* bhh_l1b  = (const float*)d_in[17];
    const float* fc1_w    = (const float*)d_in[18];
    const float* fc1_b    = (const float*)d_in[19];
    const float* fc2_w    = (const float*)d_in[20];
    const float* fc2_b    = (const float*)d_in[21];
    float* out = (float*)d_out;

    __half *gi0, *gi1;
    float *y0, *hfin;
    cudaGetSymbolAddress((void**)&gi0,  g_gi0);
    cudaGetSymbolAddress((void**)&gi1,  g_gi1);
    cudaGetSymbolAddress((void**)&y0,   g_y0);
    cudaGetSymbolAddress((void**)&hfin, g_hfin);

    {
        dim3 grid(Mrows / 128, G3 / 96, 2);
        gates_mma_kernel<128, true><<<grid, 256>>>(emb, x, Wih_l0f, Wih_l0b,
                                                   bih_l0f, bih_l0b, gi0);
    }

    scan_mma_kernel<<<dim3(64, 2), 512>>>(gi0, Whh_l0f, Whh_l0b,
                                          bhh_l0f, bhh_l0b, y0, 0);

    {
        dim3 grid(Mrows / 128, G3 / 96, 2);
        gates_mma_kernel<320, false><<<grid, 256>>>(y0, nullptr, Wih_l1f, Wih_l1b,
                                                    bih_l1f, bih_l1b, gi1);
    }

    scan_mma_kernel<<<dim3(64, 2), 512>>>(gi1, Whh_l1f, Whh_l1b,
                                          bhh_l1f, bhh_l1b, hfin, 1);

    head_kernel<<<Bb, 128>>>(hfin, fc1_w, fc1_b, fc2_w, fc2_b, out);
}